// round 7
// baseline (speedup 1.0000x reference)
#include <cuda_runtime.h>
#include <cstdint>
#include <cstddef>

// Problem constants
#define B_  2
#define S_  400
#define D_  512
#define ROWS (B_ * S_)                  // 800
#define ALIGN_OFF (S_ * B_ * D_)        // 409600

// Scratch (device globals: no allocation allowed)
__device__ float g_wq[ROWS * D_];
__device__ float g_uh[ROWS * D_];
__device__ float g_ctx[ROWS * D_];
__device__ float g_scores[ROWS * S_];

// ---------------------------------------------------------------------------
__device__ __forceinline__ float tanh_fast(float x) {
    float y;
    asm("tanh.approx.f32 %0, %1;" : "=f"(y) : "f"(x));
    return y;
}

__device__ __forceinline__ uint32_t smem_u32(const void* p) {
    uint32_t a;
    asm("{ .reg .u64 t; cvta.to.shared.u64 t, %1; cvt.u32.u64 %0, t; }"
        : "=r"(a) : "l"(p));
    return a;
}

__device__ __forceinline__ uint32_t f2tf32(float x) {   // round-to-nearest tf32
    uint32_t r;
    asm("cvt.rna.tf32.f32 %0, %1;" : "=r"(r) : "f"(x));
    return r;
}

__device__ __forceinline__ void cp_async16(uint32_t dst, const void* src, uint32_t src_bytes) {
    asm volatile("cp.async.ca.shared.global [%0], [%1], 16, %2;"
                 :: "r"(dst), "l"(src), "r"(src_bytes) : "memory");
}

__device__ __forceinline__ void mma_tf32(float* d,
                                         uint32_t a0, uint32_t a1, uint32_t a2, uint32_t a3,
                                         uint32_t b0, uint32_t b1) {
    asm volatile(
        "mma.sync.aligned.m16n8k8.row.col.f32.tf32.tf32.f32 "
        "{%0,%1,%2,%3}, {%4,%5,%6,%7}, {%8,%9}, {%0,%1,%2,%3};"
        : "+f"(d[0]), "+f"(d[1]), "+f"(d[2]), "+f"(d[3])
        : "r"(a0), "r"(a1), "r"(a2), "r"(a3), "r"(b0), "r"(b1));
}

struct GemmArgs {
    const float* A;     // [M, KA] row-major, lda
    const float* A2;    // [M, K-KA] row-major, lda (concat tail)
    const float* B;     // [K, N] row-major, ldb
    const float* bias;  // [N] or null
    float* C;
};

// ---------------------------------------------------------------------------
// tf32 mma.sync GEMM, 64x64 CTA tile, 256 threads (8 warps: 2M x 4N, each
// warp 32x16). BK=16, cp.async 4-stage pipeline (prefetch distance 3).
// blockIdx.z selects g0/g1. cmode 0: C[r*ldc+c]; cmode 1: [T,B,D] scatter.
// ---------------------------------------------------------------------------
#define ASTR 20
#define BSTR 72
#define NSTAGE 4

__global__ void __launch_bounds__(256, 1) gemm_mma64(
    GemmArgs g0, GemmArgs g1, int lda, int KA, int ldb, int ldc, int cmode,
    int M, int N, int K)
{
    __shared__ float As[NSTAGE][64][ASTR];
    __shared__ float Bs[NSTAGE][16][BSTR];

    const GemmArgs g = blockIdx.z ? g1 : g0;

    const int tid  = threadIdx.x;                  // 0..255
    const int warp = tid >> 5, lane = tid & 31;
    const int q = lane >> 2, r = lane & 3;
    const int wm = warp >> 2;                      // 0..1 : M offset 32*wm
    const int wn = warp & 3;                       // 0..3 : N offset 16*wn
    const int row0 = blockIdx.y * 64;
    const int col0 = blockIdx.x * 64;

    const uint32_t asm_base = smem_u32(&As[0][0][0]);
    const uint32_t bsm_base = smem_u32(&Bs[0][0][0]);

    float acc[2][2][4];
    #pragma unroll
    for (int i = 0; i < 2; ++i)
        #pragma unroll
        for (int j = 0; j < 2; ++j)
            #pragma unroll
            for (int k = 0; k < 4; ++k) acc[i][j][k] = 0.f;

    const int nc = K >> 4;     // K % 16 == 0 for all calls

    // loader coords (1 A chunk + 1 B chunk per thread per stage)
    const int arow = tid >> 2;            // 0..63
    const int ak   = (tid & 3) << 2;      // 0,4,8,12
    const int ar_g = row0 + arow;
    const int arc  = (ar_g < M) ? ar_g : (M - 1);
    const uint32_t apred = (ar_g < M) ? 16u : 0u;
    const int brow = tid >> 4;            // 0..15
    const int bn   = (tid & 15) << 2;     // 0..60

    // Always commits a group (possibly empty) so wait_group counts stay exact.
    auto load_stage = [&](int chunk, int buf) {
        if (chunk < nc) {
            const int k0 = chunk << 4;
            {
                const int kk = k0 + ak;
                const float* src = (kk < KA) ? g.A  + (size_t)arc * lda + kk
                                             : g.A2 + (size_t)arc * lda + (kk - KA);
                const uint32_t dst = asm_base +
                    (uint32_t)(buf * 64 * ASTR + arow * ASTR + ak) * 4u;
                cp_async16(dst, src, apred);
            }
            {
                const float* src = g.B + (size_t)(k0 + brow) * ldb + col0 + bn;
                const uint32_t dst = bsm_base +
                    (uint32_t)(buf * 16 * BSTR + brow * BSTR + bn) * 4u;
                cp_async16(dst, src, 16u);
            }
        }
        asm volatile("cp.async.commit_group;" ::: "memory");
    };

    // prologue: stages 0..2 in flight
    load_stage(0, 0);
    load_stage(1, 1);
    load_stage(2, 2);

    for (int c = 0; c < nc; ++c) {
        const int buf = c & (NSTAGE - 1);
        asm volatile("cp.async.wait_group 2;" ::: "memory");
        __syncthreads();

        #pragma unroll
        for (int ks = 0; ks < 2; ++ks) {
            const int kb = ks * 8;
            uint32_t af[2][4];
            #pragma unroll
            for (int mt = 0; mt < 2; ++mt) {
                const int mrow = wm * 32 + mt * 16 + q;
                af[mt][0] = f2tf32(As[buf][mrow    ][kb + r    ]);
                af[mt][1] = f2tf32(As[buf][mrow + 8][kb + r    ]);
                af[mt][2] = f2tf32(As[buf][mrow    ][kb + r + 4]);
                af[mt][3] = f2tf32(As[buf][mrow + 8][kb + r + 4]);
            }
            uint32_t bf[2][2];
            #pragma unroll
            for (int nt = 0; nt < 2; ++nt) {
                const int ncol = wn * 16 + nt * 8 + q;
                bf[nt][0] = f2tf32(Bs[buf][kb + r    ][ncol]);
                bf[nt][1] = f2tf32(Bs[buf][kb + r + 4][ncol]);
            }
            #pragma unroll
            for (int mt = 0; mt < 2; ++mt)
                #pragma unroll
                for (int nt = 0; nt < 2; ++nt)
                    mma_tf32(acc[mt][nt],
                             af[mt][0], af[mt][1], af[mt][2], af[mt][3],
                             bf[nt][0], bf[nt][1]);
        }
        // issue next stage (buffer (c+3)&3 was fully consumed at iteration c-1)
        load_stage(c + 3, (c + 3) & (NSTAGE - 1));
    }

    // ---- epilogue ----
    float bvals[2][2];
    #pragma unroll
    for (int nt = 0; nt < 2; ++nt) {
        const int cc = col0 + wn * 16 + nt * 8 + r * 2;
        bvals[nt][0] = g.bias ? __ldg(g.bias + cc)     : 0.f;
        bvals[nt][1] = g.bias ? __ldg(g.bias + cc + 1) : 0.f;
    }
    #pragma unroll
    for (int mt = 0; mt < 2; ++mt) {
        #pragma unroll
        for (int rh = 0; rh < 2; ++rh) {
            const int rr = row0 + wm * 32 + mt * 16 + rh * 8 + q;
            if (rr >= M) continue;
            float* rowp;
            if (cmode == 0) rowp = g.C + (size_t)rr * ldc;
            else {
                const int t = rr % S_, bb = rr / S_;
                rowp = g.C + (size_t)t * (B_ * D_) + (size_t)bb * D_;
            }
            #pragma unroll
            for (int nt = 0; nt < 2; ++nt) {
                const int cc = col0 + wn * 16 + nt * 8 + r * 2;
                float2 o;
                o.x = acc[mt][nt][rh * 2 + 0] + bvals[nt][0];
                o.y = acc[mt][nt][rh * 2 + 1] + bvals[nt][1];
                *(float2*)(rowp + cc) = o;
            }
        }
    }
}

// ---------------------------------------------------------------------------
// Scores: score[b,t,s] = sum_e v[e] * tanh(wq[b,t,e] + uh[b,s,e])
// 8 t per CTA; each warp processes 4 s at a time (q reused from regs).
// grid: (5, 50, 2), 256 threads. MUFU(tanh)-bound by design.
// ---------------------------------------------------------------------------
__global__ void __launch_bounds__(256) scores_kernel(
    const float* __restrict__ wq, const float* __restrict__ uh,
    const float* __restrict__ v, float* __restrict__ scores)
{
    const int b = blockIdx.z, t0 = blockIdx.y * 8;
    const int sbase = blockIdx.x * 96;
    __shared__ float qsm[8][D_];
    __shared__ float vsm[D_];
    const int tid = threadIdx.x;
    for (int i = tid; i < 8 * D_; i += 256)
        qsm[i >> 9][i & 511] = wq[((size_t)(b * S_ + t0 + (i >> 9))) * D_ + (i & 511)];
    for (int i = tid; i < D_; i += 256) vsm[i] = v[i];
    __syncthreads();
    const int warp = tid >> 5, lane = tid & 31;

    for (int sg = 0; sg < 3; ++sg) {
        const int s0 = sbase + sg * 32 + warp * 4;
        const float* up[4];
        #pragma unroll
        for (int j = 0; j < 4; ++j) {
            int sj = s0 + j; if (sj > S_ - 1) sj = S_ - 1;   // clamp (discard at store)
            up[j] = uh + ((size_t)b * S_ + sj) * D_;
        }
        float acc[8][4];
        #pragma unroll
        for (int t = 0; t < 8; ++t)
            #pragma unroll
            for (int j = 0; j < 4; ++j) acc[t][j] = 0.f;

        for (int i = 0; i < 16; ++i) {
            const int e = i * 32 + lane;
            const float ve = vsm[e];
            float qv[8];
            #pragma unroll
            for (int t = 0; t < 8; ++t) qv[t] = qsm[t][e];
            #pragma unroll
            for (int j = 0; j < 4; ++j) {
                const float u = __ldg(up[j] + e);
                #pragma unroll
                for (int t = 0; t < 8; ++t)
                    acc[t][j] = fmaf(ve, tanh_fast(qv[t] + u), acc[t][j]);
            }
        }
        #pragma unroll
        for (int t = 0; t < 8; ++t)
            #pragma unroll
            for (int j = 0; j < 4; ++j) {
                float a = acc[t][j];
                a += __shfl_xor_sync(0xffffffffu, a, 16);
                a += __shfl_xor_sync(0xffffffffu, a, 8);
                a += __shfl_xor_sync(0xffffffffu, a, 4);
                a += __shfl_xor_sync(0xffffffffu, a, 2);
                a += __shfl_xor_sync(0xffffffffu, a, 1);
                if (lane == t * 4 + j && s0 + j < S_)
                    scores[((size_t)(b * S_ + t0 + t)) * S_ + s0 + j] = a;
            }
    }
}

// ---------------------------------------------------------------------------
// Masked softmax per (b,t) row; writes align to d_out in [t,B,S] layout.
// ---------------------------------------------------------------------------
__global__ void softmax_kernel(const float* __restrict__ scores, const int* __restrict__ lens,
                               float* __restrict__ align_out)
{
    const int t = blockIdx.x;
    const int b = blockIdx.y;
    const int len = lens[b];
    const int tid = threadIdx.x;   // 128

    __shared__ float sm[S_];
    __shared__ float red[4];

    const float* srow = scores + ((size_t)(b * S_ + t)) * S_;

    float mx = -1e30f;
    for (int s = tid; s < S_; s += 128) {
        const bool ok = (s < len) && (s != t);
        const float val = ok ? srow[s] : -1e30f;
        sm[s] = val;
        mx = fmaxf(mx, val);
    }
    #pragma unroll
    for (int o = 16; o; o >>= 1) mx = fmaxf(mx, __shfl_xor_sync(0xffffffffu, mx, o));
    if ((tid & 31) == 0) red[tid >> 5] = mx;
    __syncthreads();
    const float bm = fmaxf(fmaxf(red[0], red[1]), fmaxf(red[2], red[3]));
    __syncthreads();

    float sum = 0.0f;
    for (int s = tid; s < S_; s += 128) {
        const float val = sm[s];
        const float e = (val > -1e29f) ? __expf(val - bm) : 0.0f;
        sm[s] = e;
        sum += e;
    }
    #pragma unroll
    for (int o = 16; o; o >>= 1) sum += __shfl_xor_sync(0xffffffffu, sum, o);
    if ((tid & 31) == 0) red[tid >> 5] = sum;
    __syncthreads();
    const float inv = 1.0f / (red[0] + red[1] + red[2] + red[3]);

    for (int s = tid; s < S_; s += 128)
        align_out[(size_t)t * (B_ * S_) + (size_t)b * S_ + s] = sm[s] * inv;
}

// ---------------------------------------------------------------------------
extern "C" void kernel_launch(void* const* d_in, const int* in_sizes, int n_in,
                              void* d_out, int out_size)
{
    const float* input  = (const float*)d_in[0];
    const float* memory = (const float*)d_in[1];
    const int*   lens   = (const int*)d_in[2];
    const float* Wq     = (const float*)d_in[3];
    const float* bq     = (const float*)d_in[4];
    const float* Wc     = (const float*)d_in[5];
    const float* v      = (const float*)d_in[6];
    const float* Wout   = (const float*)d_in[7];
    const float* bout   = (const float*)d_in[8];
    float* out = (float*)d_out;

    float *wq_p, *uh_p, *ctx_p, *sc_p;
    cudaGetSymbolAddress((void**)&wq_p,  g_wq);
    cudaGetSymbolAddress((void**)&uh_p,  g_uh);
    cudaGetSymbolAddress((void**)&ctx_p, g_ctx);
    cudaGetSymbolAddress((void**)&sc_p,  g_scores);

    // 1) fused: z=0 -> wq = input@Wq + bq; z=1 -> uh = memory@Wc
    {
        GemmArgs gq{input,  input,  Wq, bq,      wq_p};
        GemmArgs gu{memory, memory, Wc, nullptr, uh_p};
        gemm_mma64<<<dim3(8, 13, 2), 256>>>(gq, gu, 512, 512, 512, 512, 0, 800, 512, 512);
    }
    // 2) scores
    scores_kernel<<<dim3(5, 50, 2), 256>>>(wq_p, uh_p, v, sc_p);
    // 3) masked softmax -> align (d_out tail)
    softmax_kernel<<<dim3(400, 2), 128>>>(sc_p, lens, out + ALIGN_OFF);
    // 4) context: c[b] = align[b] @ memory[b]  (align rows stride 800; z = batch)
    {
        GemmArgs c0{out + ALIGN_OFF,      out + ALIGN_OFF,      memory,           nullptr, ctx_p};
        GemmArgs c1{out + ALIGN_OFF + S_, out + ALIGN_OFF + S_, memory + S_ * D_, nullptr, ctx_p + S_ * D_};
        gemm_mma64<<<dim3(8, 7, 2), 256>>>(c0, c1, 800, 400, 512, 512, 0, 400, 512, 400);
    }
    // 5) attn_h = [ctx | input] @ Wout + bout -> [T,B,D] in d_out
    {
        GemmArgs go{ctx_p, input, Wout, bout, out};
        gemm_mma64<<<dim3(8, 13, 1), 256>>>(go, go, 512, 512, 512, 512, 1, 800, 512, 1024);
    }
}

// round 8
// speedup vs baseline: 1.1617x; 1.1617x over previous
#include <cuda_runtime.h>
#include <cuda_fp16.h>
#include <cstdint>
#include <cstddef>

// Problem constants
#define B_  2
#define S_  400
#define D_  512
#define ROWS (B_ * S_)                  // 800
#define ALIGN_OFF (S_ * B_ * D_)        // 409600

// Scratch (device globals: no allocation allowed)
__device__ float  g_wq[ROWS * D_];
__device__ float  g_uh[ROWS * D_];
__device__ float  g_scores[ROWS * S_];
__device__ __half g_in_h[ROWS * D_];
__device__ __half g_mem_h[ROWS * D_];
__device__ __half g_memT_h[B_ * D_ * S_];      // per b: [512][400]
__device__ __half g_WqT[D_ * D_];              // [n][k]
__device__ __half g_WcT[D_ * D_];
__device__ __half g_WoutT[D_ * 2 * D_];        // [512][1024]
__device__ __half g_ctx_h[ROWS * D_];
__device__ __half g_align_h[S_ * B_ * S_];     // [t][b][s]

// ---------------------------------------------------------------------------
__device__ __forceinline__ float tanh_fast(float x) {
    float y;
    asm("tanh.approx.f32 %0, %1;" : "=f"(y) : "f"(x));
    return y;
}

__device__ __forceinline__ uint32_t smem_u32(const void* p) {
    uint32_t a;
    asm("{ .reg .u64 t; cvta.to.shared.u64 t, %1; cvt.u32.u64 %0, t; }"
        : "=r"(a) : "l"(p));
    return a;
}

#define MBAR_INIT(mbar, cnt) \
    asm volatile("mbarrier.init.shared.b64 [%0], %1;" \
        :: "r"((uint32_t)(mbar)), "r"((uint32_t)(cnt)) : "memory")

#define MBAR_WAIT(mbar, parity) do { \
    uint32_t _m = (uint32_t)(mbar); uint32_t _p = (uint32_t)(parity); uint32_t _d; \
    asm volatile("{\n\t.reg .pred p;\n\t" \
        "mbarrier.try_wait.parity.acquire.cta.shared::cta.b64 p, [%1], %2;\n\t" \
        "selp.b32 %0, 1, 0, p;\n\t}" : "=r"(_d) : "r"(_m), "r"(_p) : "memory"); \
    if (!_d) { \
        asm volatile("{\n\t.reg .pred P1;\n\t" \
            "WL_%=:\n\t" \
            "mbarrier.try_wait.parity.acquire.cta.shared::cta.b64 P1, [%0], %1, 0x989680;\n\t" \
            "@P1 bra.uni WD_%=;\n\t" \
            "bra.uni WL_%=;\n\t" \
            "WD_%=:\n\t}" :: "r"(_m), "r"(_p) : "memory"); \
    } \
} while (0)

__device__ __forceinline__ void bulk_cp(uint32_t dst, const void* src,
                                        uint32_t bytes, uint32_t mbar) {
    asm volatile(
        "cp.async.bulk.shared::cluster.global.mbarrier::complete_tx::bytes "
        "[%0], [%1], %2, [%3];"
        :: "r"(dst), "l"(src), "r"(bytes), "r"(mbar) : "memory");
}

__device__ __forceinline__ void ldsm_x4(uint32_t* r, uint32_t addr) {
    asm volatile("ldmatrix.sync.aligned.m8n8.x4.shared.b16 {%0,%1,%2,%3}, [%4];"
                 : "=r"(r[0]), "=r"(r[1]), "=r"(r[2]), "=r"(r[3]) : "r"(addr));
}

__device__ __forceinline__ void mma16(float* d, const uint32_t* a,
                                      uint32_t b0, uint32_t b1) {
    asm volatile(
        "mma.sync.aligned.m16n8k16.row.col.f32.f16.f16.f32 "
        "{%0,%1,%2,%3}, {%4,%5,%6,%7}, {%8,%9}, {%0,%1,%2,%3};"
        : "+f"(d[0]), "+f"(d[1]), "+f"(d[2]), "+f"(d[3])
        : "r"(a[0]), "r"(a[1]), "r"(a[2]), "r"(a[3]), "r"(b0), "r"(b1));
}

struct GemmArgs {
    const __half* A;      // [M, KA] row-major, lda (halves)
    const __half* A2;     // [M, K-KA] row-major, lda (concat tail)
    const __half* Bt;     // [N, K] row-major, ldb  (B transposed)
    const float*  bias;   // [N] or null
    float*        C;      // f32 out (omode 0/1)
    __half*       Ch;     // f16 out (omode 2)
};

// ---------------------------------------------------------------------------
// fp16 mma.sync GEMM, 64x64 CTA tile, 256 threads (8 warps: 2M x 4N, each
// warp 32x16). K staged by KS via cp.async.bulk (one bulk per tile row) +
// mbarrier; operands read via ldmatrix.x4 (B pre-transposed -> non-trans).
// omode 0: C[r*ldc+c] f32; 1: [T,B,D] scatter f32; 2: Ch[r*ldc+c] f16.
// Requires: KS%16==0, KA%KS==0, bufs in {1,2}, smem = bufs*2*64*(KS+8)*2 B.
// ---------------------------------------------------------------------------
__global__ void __launch_bounds__(256, 1) gemm_f16(
    GemmArgs ga0, GemmArgs ga1, int lda, int KA, int ldb, int ldc,
    int omode, int M, int K, int KS, int bufs)
{
    extern __shared__ __half sh[];
    __shared__ uint64_t mbars[2];

    const GemmArgs g = blockIdx.z ? ga1 : ga0;
    const int tid = threadIdx.x, warp = tid >> 5, lane = tid & 31;
    const int q = lane >> 2, r = lane & 3;
    const int wm = warp >> 2;                  // 0..1 : M offset 32*wm
    const int wn = warp & 3;                   // 0..3 : N offset 16*wn
    const int row0 = blockIdx.y * 64;
    const int col0 = blockIdx.x * 64;
    const int RS = KS + 8;                     // halves per smem row
    const int ns = K / KS;
    const uint32_t shb = smem_u32(sh);
    const uint32_t mb  = smem_u32(mbars);
    const uint32_t boff = (uint32_t)bufs * 64u * (uint32_t)RS;   // halves

    if (tid < 2) MBAR_INIT(mb + tid * 8, 1);
    __syncthreads();

    // loader: threads 0-63 -> A rows, 64-127 -> B rows
    const int  lrow  = tid & 63;
    const bool isA   = tid < 64;
    const bool isLd  = tid < 128;
    const int  arow_g = row0 + lrow;
    const int  arow_c = (arow_g < M) ? arow_g : (M - 1);
    const uint32_t stage_bytes = (uint32_t)KS * 2u * 128u;   // 128 rows x KS halves

    auto issue = [&](int c) {
        const int bi = c & (bufs - 1);
        const uint32_t mbar = mb + (uint32_t)(c & 1) * 8u;
        if (tid == 0)
            asm volatile("mbarrier.arrive.expect_tx.shared.b64 _, [%0], %1;"
                         :: "r"(mbar), "r"(stage_bytes) : "memory");
        if (isLd) {
            const int k0 = c * KS;
            const __half* src;
            uint32_t dst;
            if (isA) {
                const __half* Ab = (k0 < KA) ? g.A : g.A2;
                const int kk = (k0 < KA) ? k0 : (k0 - KA);
                src = Ab + (size_t)arow_c * lda + kk;
                dst = shb + (uint32_t)((bi * 64 + lrow) * RS) * 2u;
            } else {
                src = g.Bt + (size_t)(col0 + lrow) * ldb + (size_t)c * KS;
                dst = shb + (boff + (uint32_t)((bi * 64 + lrow) * RS)) * 2u;
            }
            bulk_cp(dst, src, (uint32_t)KS * 2u, mbar);
        }
    };

    float acc[2][2][4];
    #pragma unroll
    for (int i = 0; i < 2; ++i)
        #pragma unroll
        for (int j2 = 0; j2 < 2; ++j2)
            #pragma unroll
            for (int k2 = 0; k2 < 4; ++k2) acc[i][j2][k2] = 0.f;

    int ph0 = 0, ph1 = 0;
    issue(0);

    const int j   = lane & 7;
    const int sm8 = (lane >> 3) & 1;
    const int sk8 = (lane >> 4) & 1;

    for (int c = 0; c < ns; ++c) {
        if (c + 1 < ns) issue(c + 1);
        if ((c & 1) == 0) { MBAR_WAIT(mb,     ph0); ph0 ^= 1; }
        else              { MBAR_WAIT(mb + 8, ph1); ph1 ^= 1; }

        const int bi = c & (bufs - 1);
        const uint32_t Ab = shb + (uint32_t)(bi * 64 * RS) * 2u;
        const uint32_t Bb = shb + (boff + (uint32_t)(bi * 64 * RS)) * 2u;
        const int steps = KS >> 4;

        const uint32_t arow_off = (uint32_t)((wm * 32 + j + 8 * sm8) * RS + 8 * sk8) * 2u;
        const uint32_t brow_off = (uint32_t)((wn * 16 + j + 8 * sm8) * RS + 8 * sk8) * 2u;

        for (int s = 0; s < steps; ++s) {
            const uint32_t kb2 = (uint32_t)(s * 16) * 2u;
            uint32_t a0[4], a1[4], bb[4];
            ldsm_x4(a0, Ab + arow_off + kb2);
            ldsm_x4(a1, Ab + arow_off + kb2 + (uint32_t)(16 * RS) * 2u);
            ldsm_x4(bb, Bb + brow_off + kb2);
            mma16(acc[0][0], a0, bb[0], bb[2]);
            mma16(acc[0][1], a0, bb[1], bb[3]);
            mma16(acc[1][0], a1, bb[0], bb[2]);
            mma16(acc[1][1], a1, bb[1], bb[3]);
        }
        __syncthreads();
    }

    // ---- epilogue ----
    float bv[2][2];
    #pragma unroll
    for (int nt = 0; nt < 2; ++nt) {
        const int cc = col0 + wn * 16 + nt * 8 + r * 2;
        bv[nt][0] = g.bias ? __ldg(g.bias + cc)     : 0.f;
        bv[nt][1] = g.bias ? __ldg(g.bias + cc + 1) : 0.f;
    }
    #pragma unroll
    for (int mt = 0; mt < 2; ++mt) {
        #pragma unroll
        for (int rh = 0; rh < 2; ++rh) {
            const int rr = row0 + wm * 32 + mt * 16 + rh * 8 + q;
            if (rr >= M) continue;
            #pragma unroll
            for (int nt = 0; nt < 2; ++nt) {
                const int cc = col0 + wn * 16 + nt * 8 + r * 2;
                const float ox = acc[mt][nt][rh * 2 + 0] + bv[nt][0];
                const float oy = acc[mt][nt][rh * 2 + 1] + bv[nt][1];
                if (omode == 2) {
                    __half2* dp = (__half2*)(g.Ch + (size_t)rr * ldc + cc);
                    *dp = __floats2half2_rn(ox, oy);
                } else {
                    float* rowp;
                    if (omode == 0) rowp = g.C + (size_t)rr * ldc;
                    else {
                        const int t = rr % S_, bbn = rr / S_;
                        rowp = g.C + (size_t)t * (B_ * D_) + (size_t)bbn * D_;
                    }
                    *(float2*)(rowp + cc) = make_float2(ox, oy);
                }
            }
        }
    }
}

// ---------------------------------------------------------------------------
// Prep: elementwise f32 -> f16 for input & memory
// ---------------------------------------------------------------------------
__global__ void conv_h(const float4* __restrict__ a, __half2* __restrict__ ah,
                       const float4* __restrict__ b, __half2* __restrict__ bh, int n4)
{
    const int i = blockIdx.x * 256 + threadIdx.x;
    if (i < n4) {
        float4 v = a[i];
        ah[2 * i]     = __floats2half2_rn(v.x, v.y);
        ah[2 * i + 1] = __floats2half2_rn(v.z, v.w);
        v = b[i];
        bh[2 * i]     = __floats2half2_rn(v.x, v.y);
        bh[2 * i + 1] = __floats2half2_rn(v.z, v.w);
    }
}

// ---------------------------------------------------------------------------
// Prep: transpose + convert: out[c][r] = (half)in[r][c], per z batch
// ---------------------------------------------------------------------------
__global__ void trans_h(const float* __restrict__ in, __half* __restrict__ out,
                        int R, int C, int inz, int outz)
{
    __shared__ float t[32][33];
    const float* I = in + (size_t)blockIdx.z * inz;
    __half* O = out + (size_t)blockIdx.z * outz;
    const int c0 = blockIdx.x * 32, r0 = blockIdx.y * 32;
    const int x = threadIdx.x, y = threadIdx.y;    // 32 x 8
    #pragma unroll
    for (int d = 0; d < 32; d += 8) {
        const int rr = r0 + y + d, cc = c0 + x;
        t[y + d][x] = (rr < R && cc < C) ? I[(size_t)rr * C + cc] : 0.f;
    }
    __syncthreads();
    #pragma unroll
    for (int d = 0; d < 32; d += 8) {
        const int orow = c0 + y + d;   // original col
        const int ocol = r0 + x;       // original row
        if (orow < C && ocol < R)
            O[(size_t)orow * R + ocol] = __float2half(t[x][y + d]);
    }
}

// ---------------------------------------------------------------------------
// Scores: score[b,t,s] = sum_e v[e] * tanh(wq[b,t,e] + uh[b,s,e])
// ---------------------------------------------------------------------------
__global__ void __launch_bounds__(256) scores_kernel(
    const float* __restrict__ wq, const float* __restrict__ uh,
    const float* __restrict__ v, float* __restrict__ scores)
{
    const int b = blockIdx.z, t0 = blockIdx.y * 8;
    const int sbase = blockIdx.x * 96;
    __shared__ float qsm[8][D_];
    __shared__ float vsm[D_];
    const int tid = threadIdx.x;
    for (int i = tid; i < 8 * D_; i += 256)
        qsm[i >> 9][i & 511] = wq[((size_t)(b * S_ + t0 + (i >> 9))) * D_ + (i & 511)];
    for (int i = tid; i < D_; i += 256) vsm[i] = v[i];
    __syncthreads();
    const int warp = tid >> 5, lane = tid & 31;

    for (int sg = 0; sg < 3; ++sg) {
        const int s0 = sbase + sg * 32 + warp * 4;
        const float* up[4];
        #pragma unroll
        for (int j = 0; j < 4; ++j) {
            int sj = s0 + j; if (sj > S_ - 1) sj = S_ - 1;
            up[j] = uh + ((size_t)b * S_ + sj) * D_;
        }
        float acc[8][4];
        #pragma unroll
        for (int t = 0; t < 8; ++t)
            #pragma unroll
            for (int j = 0; j < 4; ++j) acc[t][j] = 0.f;

        for (int i = 0; i < 16; ++i) {
            const int e = i * 32 + lane;
            const float ve = vsm[e];
            float qv[8];
            #pragma unroll
            for (int t = 0; t < 8; ++t) qv[t] = qsm[t][e];
            #pragma unroll
            for (int j = 0; j < 4; ++j) {
                const float u = __ldg(up[j] + e);
                #pragma unroll
                for (int t = 0; t < 8; ++t)
                    acc[t][j] = fmaf(ve, tanh_fast(qv[t] + u), acc[t][j]);
            }
        }
        #pragma unroll
        for (int t = 0; t < 8; ++t)
            #pragma unroll
            for (int j = 0; j < 4; ++j) {
                float a = acc[t][j];
                a += __shfl_xor_sync(0xffffffffu, a, 16);
                a += __shfl_xor_sync(0xffffffffu, a, 8);
                a += __shfl_xor_sync(0xffffffffu, a, 4);
                a += __shfl_xor_sync(0xffffffffu, a, 2);
                a += __shfl_xor_sync(0xffffffffu, a, 1);
                if (lane == t * 4 + j && s0 + j < S_)
                    scores[((size_t)(b * S_ + t0 + t)) * S_ + s0 + j] = a;
            }
    }
}

// ---------------------------------------------------------------------------
// Masked softmax; writes align f32 to d_out [t,B,S] and f16 copy for ctx gemm.
// ---------------------------------------------------------------------------
__global__ void softmax_kernel(const float* __restrict__ scores, const int* __restrict__ lens,
                               float* __restrict__ align_out, __half* __restrict__ align_h)
{
    const int t = blockIdx.x;
    const int b = blockIdx.y;
    const int len = lens[b];
    const int tid = threadIdx.x;   // 128

    __shared__ float sm[S_];
    __shared__ float red[4];

    const float* srow = scores + ((size_t)(b * S_ + t)) * S_;

    float mx = -1e30f;
    for (int s = tid; s < S_; s += 128) {
        const bool ok = (s < len) && (s != t);
        const float val = ok ? srow[s] : -1e30f;
        sm[s] = val;
        mx = fmaxf(mx, val);
    }
    #pragma unroll
    for (int o = 16; o; o >>= 1) mx = fmaxf(mx, __shfl_xor_sync(0xffffffffu, mx, o));
    if ((tid & 31) == 0) red[tid >> 5] = mx;
    __syncthreads();
    const float bm = fmaxf(fmaxf(red[0], red[1]), fmaxf(red[2], red[3]));
    __syncthreads();

    float sum = 0.0f;
    for (int s = tid; s < S_; s += 128) {
        const float val = sm[s];
        const float e = (val > -1e29f) ? __expf(val - bm) : 0.0f;
        sm[s] = e;
        sum += e;
    }
    #pragma unroll
    for (int o = 16; o; o >>= 1) sum += __shfl_xor_sync(0xffffffffu, sum, o);
    if ((tid & 31) == 0) red[tid >> 5] = sum;
    __syncthreads();
    const float inv = 1.0f / (red[0] + red[1] + red[2] + red[3]);

    for (int s = tid; s < S_; s += 128) {
        const float a = sm[s] * inv;
        align_out[(size_t)t * (B_ * S_) + (size_t)b * S_ + s] = a;
        align_h[(size_t)t * (B_ * S_) + (size_t)b * S_ + s]   = __float2half(a);
    }
}

// ---------------------------------------------------------------------------
extern "C" void kernel_launch(void* const* d_in, const int* in_sizes, int n_in,
                              void* d_out, int out_size)
{
    const float* input  = (const float*)d_in[0];
    const float* memory = (const float*)d_in[1];
    const int*   lens   = (const int*)d_in[2];
    const float* Wq     = (const float*)d_in[3];
    const float* bq     = (const float*)d_in[4];
    const float* Wc     = (const float*)d_in[5];
    const float* v      = (const float*)d_in[6];
    const float* Wout   = (const float*)d_in[7];
    const float* bout   = (const float*)d_in[8];
    float* out = (float*)d_out;

    float *wq_p, *uh_p, *sc_p;
    __half *in_h, *mem_h, *memT_h, *WqT, *WcT, *WoutT, *ctx_h, *align_h;
    cudaGetSymbolAddress((void**)&wq_p,    g_wq);
    cudaGetSymbolAddress((void**)&uh_p,    g_uh);
    cudaGetSymbolAddress((void**)&sc_p,    g_scores);
    cudaGetSymbolAddress((void**)&in_h,    g_in_h);
    cudaGetSymbolAddress((void**)&mem_h,   g_mem_h);
    cudaGetSymbolAddress((void**)&memT_h,  g_memT_h);
    cudaGetSymbolAddress((void**)&WqT,     g_WqT);
    cudaGetSymbolAddress((void**)&WcT,     g_WcT);
    cudaGetSymbolAddress((void**)&WoutT,   g_WoutT);
    cudaGetSymbolAddress((void**)&ctx_h,   g_ctx_h);
    cudaGetSymbolAddress((void**)&align_h, g_align_h);

    static bool attr_set = false;
    if (!attr_set) {
        cudaFuncSetAttribute(gemm_f16, cudaFuncAttributeMaxDynamicSharedMemorySize,
                             2 * 2 * 64 * (256 + 8) * 2);   // 135168
        attr_set = true;
    }

    // ---- prep ----
    conv_h<<<400, 256>>>((const float4*)input, (__half2*)in_h,
                         (const float4*)memory, (__half2*)mem_h, ROWS * D_ / 4);
    dim3 tb(32, 8);
    trans_h<<<dim3(16, 16, 1), tb>>>(Wq,   WqT,   512, 512, 0, 0);
    trans_h<<<dim3(16, 16, 1), tb>>>(Wc,   WcT,   512, 512, 0, 0);
    trans_h<<<dim3(16, 32, 1), tb>>>(Wout, WoutT, 1024, 512, 0, 0);
    trans_h<<<dim3(16, 13, 2), tb>>>(memory, memT_h, 400, 512, 400 * 512, 512 * 400);

    // ---- 1) fused: z=0 -> wq = input@Wq + bq; z=1 -> uh = memory@Wc ----
    {
        GemmArgs gq{in_h,  in_h,  WqT, bq,      wq_p, nullptr};
        GemmArgs gu{mem_h, mem_h, WcT, nullptr, uh_p, nullptr};
        gemm_f16<<<dim3(8, 13, 2), 256, 2 * 2 * 64 * 264 * 2>>>(
            gq, gu, 512, 512, 512, 512, 0, 800, 512, 256, 2);
    }
    // ---- 2) scores ----
    scores_kernel<<<dim3(5, 50, 2), 256>>>(wq_p, uh_p, v, sc_p);
    // ---- 3) masked softmax -> align (f32 in d_out, f16 copy) ----
    softmax_kernel<<<dim3(400, 2), 128>>>(sc_p, lens, out + ALIGN_OFF, align_h);
    // ---- 4) context: c[b] = align[b] @ memory[b] -> ctx_h (f16) ----
    {
        GemmArgs c0{align_h,       align_h,       memT_h,             nullptr, nullptr, ctx_h};
        GemmArgs c1{align_h + S_,  align_h + S_,  memT_h + D_ * S_,   nullptr, nullptr, ctx_h + S_ * D_};
        gemm_f16<<<dim3(8, 7, 2), 256, 1 * 2 * 64 * 408 * 2>>>(
            c0, c1, 800, 400, 400, 512, 2, 400, 400, 400, 1);
    }
    // ---- 5) attn_h = [ctx | input] @ Wout + bout -> [T,B,D] in d_out ----
    {
        GemmArgs go{ctx_h, in_h, WoutT, bout, out, nullptr};
        gemm_f16<<<dim3(8, 13, 1), 256, 2 * 2 * 64 * 264 * 2>>>(
            go, go, 512, 512, 1024, 512, 1, 800, 1024, 256, 2);
    }
}

// round 9
// speedup vs baseline: 1.6985x; 1.4620x over previous
#include <cuda_runtime.h>
#include <cuda_fp16.h>
#include <cstdint>
#include <cstddef>

// Problem constants
#define B_  2
#define S_  400
#define D_  512
#define ROWS (B_ * S_)                  // 800
#define ALIGN_OFF (S_ * B_ * D_)        // 409600

// Scratch (device globals: no allocation allowed)
__device__ float  g_wq[ROWS * D_];
__device__ float  g_uh[ROWS * D_];
__device__ float  g_scores[ROWS * S_];
__device__ __half g_in_h[ROWS * D_];
__device__ __half g_mem_h[ROWS * D_];
__device__ __half g_memT_h[B_ * D_ * S_];      // per b: [512][400]
__device__ __half g_WqT[D_ * D_];              // [n][k]
__device__ __half g_WcT[D_ * D_];
__device__ __half g_WoutT[D_ * 2 * D_];        // [512][1024]
__device__ __half g_ctx_h[ROWS * D_];
__device__ __half g_align_h[S_ * B_ * S_];     // [t][b][s]

// ---------------------------------------------------------------------------
__device__ __forceinline__ float tanh_fast(float x) {
    float y;
    asm("tanh.approx.f32 %0, %1;" : "=f"(y) : "f"(x));
    return y;
}

__device__ __forceinline__ uint32_t smem_u32(const void* p) {
    uint32_t a;
    asm("{ .reg .u64 t; cvta.to.shared.u64 t, %1; cvt.u32.u64 %0, t; }"
        : "=r"(a) : "l"(p));
    return a;
}

#define MBAR_INIT(mbar, cnt) \
    asm volatile("mbarrier.init.shared.b64 [%0], %1;" \
        :: "r"((uint32_t)(mbar)), "r"((uint32_t)(cnt)) : "memory")

#define MBAR_WAIT(mbar, parity) do { \
    uint32_t _m = (uint32_t)(mbar); uint32_t _p = (uint32_t)(parity); uint32_t _d; \
    asm volatile("{\n\t.reg .pred p;\n\t" \
        "mbarrier.try_wait.parity.acquire.cta.shared::cta.b64 p, [%1], %2;\n\t" \
        "selp.b32 %0, 1, 0, p;\n\t}" : "=r"(_d) : "r"(_m), "r"(_p) : "memory"); \
    if (!_d) { \
        asm volatile("{\n\t.reg .pred P1;\n\t" \
            "WL_%=:\n\t" \
            "mbarrier.try_wait.parity.acquire.cta.shared::cta.b64 P1, [%0], %1, 0x989680;\n\t" \
            "@P1 bra.uni WD_%=;\n\t" \
            "bra.uni WL_%=;\n\t" \
            "WD_%=:\n\t}" :: "r"(_m), "r"(_p) : "memory"); \
    } \
} while (0)

__device__ __forceinline__ void bulk_cp(uint32_t dst, const void* src,
                                        uint32_t bytes, uint32_t mbar) {
    asm volatile(
        "cp.async.bulk.shared::cluster.global.mbarrier::complete_tx::bytes "
        "[%0], [%1], %2, [%3];"
        :: "r"(dst), "l"(src), "r"(bytes), "r"(mbar) : "memory");
}

__device__ __forceinline__ void ldsm_x4(uint32_t* r, uint32_t addr) {
    asm volatile("ldmatrix.sync.aligned.m8n8.x4.shared.b16 {%0,%1,%2,%3}, [%4];"
                 : "=r"(r[0]), "=r"(r[1]), "=r"(r[2]), "=r"(r[3]) : "r"(addr));
}

__device__ __forceinline__ void mma16(float* d, const uint32_t* a,
                                      uint32_t b0, uint32_t b1) {
    asm volatile(
        "mma.sync.aligned.m16n8k16.row.col.f32.f16.f16.f32 "
        "{%0,%1,%2,%3}, {%4,%5,%6,%7}, {%8,%9}, {%0,%1,%2,%3};"
        : "+f"(d[0]), "+f"(d[1]), "+f"(d[2]), "+f"(d[3])
        : "r"(a[0]), "r"(a[1]), "r"(a[2]), "r"(a[3]), "r"(b0), "r"(b1));
}

struct GemmArgs {
    const __half* A;      // [M, KA] row-major, lda (halves)
    const __half* A2;     // [M, K-KA] row-major, lda (concat tail)
    const __half* Bt;     // [N, K] row-major, ldb  (B transposed)
    const float*  bias;   // [N] or null
    float*        C;      // f32 out (omode 0/1)
    __half*       Ch;     // f16 out (omode 2)
};

// ---------------------------------------------------------------------------
// fp16 mma.sync GEMM, 64x64 CTA tile, 256 threads (8 warps: 2M x 4N).
// K staged by KS via cp.async.bulk + mbarrier; ldmatrix.x4 fragments.
// omode 0: C[r*ldc+c] f32; 1: [T,B,D] scatter f32; 2: Ch[r*ldc+c] f16.
// ---------------------------------------------------------------------------
__global__ void __launch_bounds__(256, 1) gemm_f16(
    GemmArgs ga0, GemmArgs ga1, int lda, int KA, int ldb, int ldc,
    int omode, int M, int K, int KS, int bufs)
{
    extern __shared__ __half sh[];
    __shared__ uint64_t mbars[2];

    const GemmArgs g = blockIdx.z ? ga1 : ga0;
    const int tid = threadIdx.x, warp = tid >> 5, lane = tid & 31;
    const int q = lane >> 2, r = lane & 3;
    const int wm = warp >> 2;                  // 0..1 : M offset 32*wm
    const int wn = warp & 3;                   // 0..3 : N offset 16*wn
    const int row0 = blockIdx.y * 64;
    const int col0 = blockIdx.x * 64;
    const int RS = KS + 8;                     // halves per smem row
    const int ns = K / KS;
    const uint32_t shb = smem_u32(sh);
    const uint32_t mb  = smem_u32(mbars);
    const uint32_t boff = (uint32_t)bufs * 64u * (uint32_t)RS;   // halves

    if (tid < 2) MBAR_INIT(mb + tid * 8, 1);
    __syncthreads();

    const int  lrow  = tid & 63;
    const bool isA   = tid < 64;
    const bool isLd  = tid < 128;
    const int  arow_g = row0 + lrow;
    const int  arow_c = (arow_g < M) ? arow_g : (M - 1);
    const uint32_t stage_bytes = (uint32_t)KS * 2u * 128u;

    auto issue = [&](int c) {
        const int bi = c & (bufs - 1);
        const uint32_t mbar = mb + (uint32_t)(c & 1) * 8u;
        if (tid == 0)
            asm volatile("mbarrier.arrive.expect_tx.shared.b64 _, [%0], %1;"
                         :: "r"(mbar), "r"(stage_bytes) : "memory");
        if (isLd) {
            const int k0 = c * KS;
            const __half* src;
            uint32_t dst;
            if (isA) {
                const __half* Ab = (k0 < KA) ? g.A : g.A2;
                const int kk = (k0 < KA) ? k0 : (k0 - KA);
                src = Ab + (size_t)arow_c * lda + kk;
                dst = shb + (uint32_t)((bi * 64 + lrow) * RS) * 2u;
            } else {
                src = g.Bt + (size_t)(col0 + lrow) * ldb + (size_t)c * KS;
                dst = shb + (boff + (uint32_t)((bi * 64 + lrow) * RS)) * 2u;
            }
            bulk_cp(dst, src, (uint32_t)KS * 2u, mbar);
        }
    };

    float acc[2][2][4];
    #pragma unroll
    for (int i = 0; i < 2; ++i)
        #pragma unroll
        for (int j2 = 0; j2 < 2; ++j2)
            #pragma unroll
            for (int k2 = 0; k2 < 4; ++k2) acc[i][j2][k2] = 0.f;

    int ph0 = 0, ph1 = 0;
    issue(0);

    const int j   = lane & 7;
    const int sm8 = (lane >> 3) & 1;
    const int sk8 = (lane >> 4) & 1;

    for (int c = 0; c < ns; ++c) {
        if (c + 1 < ns) issue(c + 1);
        if ((c & 1) == 0) { MBAR_WAIT(mb,     ph0); ph0 ^= 1; }
        else              { MBAR_WAIT(mb + 8, ph1); ph1 ^= 1; }

        const int bi = c & (bufs - 1);
        const uint32_t Ab = shb + (uint32_t)(bi * 64 * RS) * 2u;
        const uint32_t Bb = shb + (boff + (uint32_t)(bi * 64 * RS)) * 2u;
        const int steps = KS >> 4;

        const uint32_t arow_off = (uint32_t)((wm * 32 + j + 8 * sm8) * RS + 8 * sk8) * 2u;
        const uint32_t brow_off = (uint32_t)((wn * 16 + j + 8 * sm8) * RS + 8 * sk8) * 2u;

        for (int s = 0; s < steps; ++s) {
            const uint32_t kb2 = (uint32_t)(s * 16) * 2u;
            uint32_t a0[4], a1[4], bb[4];
            ldsm_x4(a0, Ab + arow_off + kb2);
            ldsm_x4(a1, Ab + arow_off + kb2 + (uint32_t)(16 * RS) * 2u);
            ldsm_x4(bb, Bb + brow_off + kb2);
            mma16(acc[0][0], a0, bb[0], bb[2]);
            mma16(acc[0][1], a0, bb[1], bb[3]);
            mma16(acc[1][0], a1, bb[0], bb[2]);
            mma16(acc[1][1], a1, bb[1], bb[3]);
        }
        __syncthreads();
    }

    // ---- epilogue ----
    float bv[2][2];
    #pragma unroll
    for (int nt = 0; nt < 2; ++nt) {
        const int cc = col0 + wn * 16 + nt * 8 + r * 2;
        bv[nt][0] = g.bias ? __ldg(g.bias + cc)     : 0.f;
        bv[nt][1] = g.bias ? __ldg(g.bias + cc + 1) : 0.f;
    }
    #pragma unroll
    for (int mt = 0; mt < 2; ++mt) {
        #pragma unroll
        for (int rh = 0; rh < 2; ++rh) {
            const int rr = row0 + wm * 32 + mt * 16 + rh * 8 + q;
            if (rr >= M) continue;
            #pragma unroll
            for (int nt = 0; nt < 2; ++nt) {
                const int cc = col0 + wn * 16 + nt * 8 + r * 2;
                const float ox = acc[mt][nt][rh * 2 + 0] + bv[nt][0];
                const float oy = acc[mt][nt][rh * 2 + 1] + bv[nt][1];
                if (omode == 2) {
                    __half2* dp = (__half2*)(g.Ch + (size_t)rr * ldc + cc);
                    *dp = __floats2half2_rn(ox, oy);
                } else {
                    float* rowp;
                    if (omode == 0) rowp = g.C + (size_t)rr * ldc;
                    else {
                        const int t = rr % S_, bbn = rr / S_;
                        rowp = g.C + (size_t)t * (B_ * D_) + (size_t)bbn * D_;
                    }
                    *(float2*)(rowp + cc) = make_float2(ox, oy);
                }
            }
        }
    }
}

// ---------------------------------------------------------------------------
// Fused prep: blockIdx.z selects job.
//  z=0..4: transpose+convert (Wq, Wc, Wout, mem b0, mem b1)
//  z=5:    f32->f16 convert of input & memory
// grid (16, 32, 6), 256 threads.
// ---------------------------------------------------------------------------
__global__ void prep_kernel(
    const float* __restrict__ input, const float* __restrict__ memory,
    const float* __restrict__ Wq, const float* __restrict__ Wc,
    const float* __restrict__ Wout,
    __half* __restrict__ in_h, __half* __restrict__ mem_h,
    __half* __restrict__ WqT, __half* __restrict__ WcT,
    __half* __restrict__ WoutT, __half* __restrict__ memT)
{
    const int z = blockIdx.z;
    const int tid = threadIdx.x;

    if (z == 5) {   // conv job
        const int i = (blockIdx.y * 16 + blockIdx.x) * 256 + tid;
        const int n4 = ROWS * D_ / 4;
        if (i < n4) {
            float4 v = ((const float4*)input)[i];
            ((__half2*)in_h)[2 * i]     = __floats2half2_rn(v.x, v.y);
            ((__half2*)in_h)[2 * i + 1] = __floats2half2_rn(v.z, v.w);
            v = ((const float4*)memory)[i];
            ((__half2*)mem_h)[2 * i]     = __floats2half2_rn(v.x, v.y);
            ((__half2*)mem_h)[2 * i + 1] = __floats2half2_rn(v.z, v.w);
        }
        return;
    }

    const float* I; __half* O; int R; int ylim;
    switch (z) {
        case 0: I = Wq;   O = WqT;   R = 512;  ylim = 16; break;
        case 1: I = Wc;   O = WcT;   R = 512;  ylim = 16; break;
        case 2: I = Wout; O = WoutT; R = 1024; ylim = 32; break;
        case 3: I = memory;            O = memT;            R = 400; ylim = 13; break;
        default:I = memory + 400 * 512; O = memT + 512 * 400; R = 400; ylim = 13; break;
    }
    if ((int)blockIdx.y >= ylim) return;
    const int C = 512;

    __shared__ float t[32][33];
    const int c0 = blockIdx.x * 32, r0 = blockIdx.y * 32;
    const int x = tid & 31, y = tid >> 5;    // 32 x 8
    #pragma unroll
    for (int d = 0; d < 32; d += 8) {
        const int rr = r0 + y + d, cc = c0 + x;
        t[y + d][x] = (rr < R && cc < C) ? I[(size_t)rr * C + cc] : 0.f;
    }
    __syncthreads();
    #pragma unroll
    for (int d = 0; d < 32; d += 8) {
        const int orow = c0 + y + d;   // original col
        const int ocol = r0 + x;       // original row
        if (orow < C && ocol < R)
            O[(size_t)orow * R + ocol] = __float2half(t[x][y + d]);
    }
}

// ---------------------------------------------------------------------------
// Scores: score[b,t,s] = sum_e v[e] * tanh(wq[b,t,e] + uh[b,s,e])
// CTA: 8 t-rows x 32 s-cols (warp = 4 s-cols). grid (13, 50, 2), 256 thr.
// Skips masked columns: block exits if sbase >= len[b]; warp exits if
// s0 >= len (softmax never reads those positions).
// ---------------------------------------------------------------------------
__global__ void __launch_bounds__(256) scores_kernel(
    const float* __restrict__ wq, const float* __restrict__ uh,
    const float* __restrict__ v, const int* __restrict__ lens,
    float* __restrict__ scores)
{
    const int b = blockIdx.z, t0 = blockIdx.y * 8;
    const int sbase = blockIdx.x * 32;
    const int len = lens[b];
    if (sbase >= len) return;                 // uniform across block

    __shared__ float qsm[8][D_];
    __shared__ float vsm[D_];
    const int tid = threadIdx.x;
    for (int i = tid; i < 8 * D_; i += 256)
        qsm[i >> 9][i & 511] = wq[((size_t)(b * S_ + t0 + (i >> 9))) * D_ + (i & 511)];
    for (int i = tid; i < D_; i += 256) vsm[i] = v[i];
    __syncthreads();

    const int warp = tid >> 5, lane = tid & 31;
    const int s0 = sbase + warp * 4;
    if (s0 >= len) return;                    // warp-level skip (no syncs below)

    const float* up[4];
    #pragma unroll
    for (int j = 0; j < 4; ++j) {
        int sj = s0 + j; if (sj > S_ - 1) sj = S_ - 1;   // clamp (discard at store)
        up[j] = uh + ((size_t)b * S_ + sj) * D_;
    }
    float acc[8][4];
    #pragma unroll
    for (int t = 0; t < 8; ++t)
        #pragma unroll
        for (int j = 0; j < 4; ++j) acc[t][j] = 0.f;

    for (int i = 0; i < 16; ++i) {
        const int e = i * 32 + lane;
        const float ve = vsm[e];
        float qv[8];
        #pragma unroll
        for (int t = 0; t < 8; ++t) qv[t] = qsm[t][e];
        #pragma unroll
        for (int j = 0; j < 4; ++j) {
            const float u = __ldg(up[j] + e);
            #pragma unroll
            for (int t = 0; t < 8; ++t)
                acc[t][j] = fmaf(ve, tanh_fast(qv[t] + u), acc[t][j]);
        }
    }
    #pragma unroll
    for (int t = 0; t < 8; ++t)
        #pragma unroll
        for (int j = 0; j < 4; ++j) {
            float a = acc[t][j];
            a += __shfl_xor_sync(0xffffffffu, a, 16);
            a += __shfl_xor_sync(0xffffffffu, a, 8);
            a += __shfl_xor_sync(0xffffffffu, a, 4);
            a += __shfl_xor_sync(0xffffffffu, a, 2);
            a += __shfl_xor_sync(0xffffffffu, a, 1);
            if (lane == t * 4 + j && s0 + j < S_)
                scores[((size_t)(b * S_ + t0 + t)) * S_ + s0 + j] = a;
        }
}

// ---------------------------------------------------------------------------
// Masked softmax; writes align f32 to d_out [t,B,S] and f16 copy for ctx gemm.
// ---------------------------------------------------------------------------
__global__ void softmax_kernel(const float* __restrict__ scores, const int* __restrict__ lens,
                               float* __restrict__ align_out, __half* __restrict__ align_h)
{
    const int t = blockIdx.x;
    const int b = blockIdx.y;
    const int len = lens[b];
    const int tid = threadIdx.x;   // 128

    __shared__ float sm[S_];
    __shared__ float red[4];

    const float* srow = scores + ((size_t)(b * S_ + t)) * S_;

    float mx = -1e30f;
    for (int s = tid; s < S_; s += 128) {
        const bool ok = (s < len) && (s != t);
        const float val = ok ? srow[s] : -1e30f;
        sm[s] = val;
        mx = fmaxf(mx, val);
    }
    #pragma unroll
    for (int o = 16; o; o >>= 1) mx = fmaxf(mx, __shfl_xor_sync(0xffffffffu, mx, o));
    if ((tid & 31) == 0) red[tid >> 5] = mx;
    __syncthreads();
    const float bm = fmaxf(fmaxf(red[0], red[1]), fmaxf(red[2], red[3]));
    __syncthreads();

    float sum = 0.0f;
    for (int s = tid; s < S_; s += 128) {
        const float val = sm[s];
        const float e = (val > -1e29f) ? __expf(val - bm) : 0.0f;
        sm[s] = e;
        sum += e;
    }
    #pragma unroll
    for (int o = 16; o; o >>= 1) sum += __shfl_xor_sync(0xffffffffu, sum, o);
    if ((tid & 31) == 0) red[tid >> 5] = sum;
    __syncthreads();
    const float inv = 1.0f / (red[0] + red[1] + red[2] + red[3]);

    for (int s = tid; s < S_; s += 128) {
        const float a = sm[s] * inv;
        align_out[(size_t)t * (B_ * S_) + (size_t)b * S_ + s] = a;
        align_h[(size_t)t * (B_ * S_) + (size_t)b * S_ + s]   = __float2half(a);
    }
}

// ---------------------------------------------------------------------------
extern "C" void kernel_launch(void* const* d_in, const int* in_sizes, int n_in,
                              void* d_out, int out_size)
{
    const float* input  = (const float*)d_in[0];
    const float* memory = (const float*)d_in[1];
    const int*   lens   = (const int*)d_in[2];
    const float* Wq     = (const float*)d_in[3];
    const float* bq     = (const float*)d_in[4];
    const float* Wc     = (const float*)d_in[5];
    const float* v      = (const float*)d_in[6];
    const float* Wout   = (const float*)d_in[7];
    const float* bout   = (const float*)d_in[8];
    float* out = (float*)d_out;

    float *wq_p, *uh_p, *sc_p;
    __half *in_h, *mem_h, *memT_h, *WqT, *WcT, *WoutT, *ctx_h, *align_h;
    cudaGetSymbolAddress((void**)&wq_p,    g_wq);
    cudaGetSymbolAddress((void**)&uh_p,    g_uh);
    cudaGetSymbolAddress((void**)&sc_p,    g_scores);
    cudaGetSymbolAddress((void**)&in_h,    g_in_h);
    cudaGetSymbolAddress((void**)&mem_h,   g_mem_h);
    cudaGetSymbolAddress((void**)&memT_h,  g_memT_h);
    cudaGetSymbolAddress((void**)&WqT,     g_WqT);
    cudaGetSymbolAddress((void**)&WcT,     g_WcT);
    cudaGetSymbolAddress((void**)&WoutT,   g_WoutT);
    cudaGetSymbolAddress((void**)&ctx_h,   g_ctx_h);
    cudaGetSymbolAddress((void**)&align_h, g_align_h);

    static bool attr_set = false;
    if (!attr_set) {
        cudaFuncSetAttribute(gemm_f16, cudaFuncAttributeMaxDynamicSharedMemorySize,
                             2 * 2 * 64 * (256 + 8) * 2);   // 135168
        attr_set = true;
    }

    // ---- prep (fused: 4 transposes + f32->f16 conversions) ----
    prep_kernel<<<dim3(16, 32, 6), 256>>>(
        input, memory, Wq, Wc, Wout, in_h, mem_h, WqT, WcT, WoutT, memT_h);

    // ---- 1) fused: z=0 -> wq = input@Wq + bq; z=1 -> uh = memory@Wc ----
    {
        GemmArgs gq{in_h,  in_h,  WqT, bq,      wq_p, nullptr};
        GemmArgs gu{mem_h, mem_h, WcT, nullptr, uh_p, nullptr};
        gemm_f16<<<dim3(8, 13, 2), 256, 2 * 2 * 64 * 264 * 2>>>(
            gq, gu, 512, 512, 512, 512, 0, 800, 512, 256, 2);
    }
    // ---- 2) scores (len-aware) ----
    scores_kernel<<<dim3(13, 50, 2), 256>>>(wq_p, uh_p, v, lens, sc_p);
    // ---- 3) masked softmax -> align (f32 in d_out, f16 copy) ----
    softmax_kernel<<<dim3(400, 2), 128>>>(sc_p, lens, out + ALIGN_OFF, align_h);
    // ---- 4) context: c[b] = align[b] @ memory[b] -> ctx_h (f16) ----
    {
        GemmArgs c0{align_h,       align_h,       memT_h,             nullptr, nullptr, ctx_h};
        GemmArgs c1{align_h + S_,  align_h + S_,  memT_h + D_ * S_,   nullptr, nullptr, ctx_h + S_ * D_};
        gemm_f16<<<dim3(8, 7, 2), 256, 1 * 2 * 64 * 408 * 2>>>(
            c0, c1, 800, 400, 400, 512, 2, 400, 400, 400, 1);
    }
    // ---- 5) attn_h = [ctx | input] @ Wout + bout -> [T,B,D] in d_out ----
    {
        GemmArgs go{ctx_h, in_h, WoutT, bout, out, nullptr};
        gemm_f16<<<dim3(8, 13, 1), 256, 2 * 2 * 64 * 264 * 2>>>(
            go, go, 512, 512, 1024, 512, 1, 800, 1024, 256, 2);
    }
}

// round 10
// speedup vs baseline: 1.7676x; 1.0407x over previous
#include <cuda_runtime.h>
#include <cuda_fp16.h>
#include <cstdint>
#include <cstddef>

// Problem constants
#define B_  2
#define S_  400
#define D_  512
#define ROWS (B_ * S_)                  // 800
#define ALIGN_OFF (S_ * B_ * D_)        // 409600

// Scratch (device globals: no allocation allowed)
__device__ float  g_scores[ROWS * S_];
__device__ __half g_wq_h[ROWS * D_];
__device__ __half g_uh_h[ROWS * D_];
__device__ __half g_in_h[ROWS * D_];
__device__ __half g_mem_h[ROWS * D_];
__device__ __half g_memT_h[B_ * D_ * S_];      // per b: [512][400]
__device__ __half g_WqT[D_ * D_];              // [n][k]
__device__ __half g_WcT[D_ * D_];
__device__ __half g_WoutT[D_ * 2 * D_];        // [512][1024]
__device__ __half g_ctx_h[ROWS * D_];
__device__ __half g_align_h[S_ * B_ * S_];     // [t][b][s]

// ---------------------------------------------------------------------------
__device__ __forceinline__ __half2 tanh2_fast(__half2 x) {
    uint32_t xi = *(uint32_t*)&x, yi;
    asm("tanh.approx.f16x2 %0, %1;" : "=r"(yi) : "r"(xi));
    return *(__half2*)&yi;
}

__device__ __forceinline__ uint32_t smem_u32(const void* p) {
    uint32_t a;
    asm("{ .reg .u64 t; cvta.to.shared.u64 t, %1; cvt.u32.u64 %0, t; }"
        : "=r"(a) : "l"(p));
    return a;
}

#define MBAR_INIT(mbar, cnt) \
    asm volatile("mbarrier.init.shared.b64 [%0], %1;" \
        :: "r"((uint32_t)(mbar)), "r"((uint32_t)(cnt)) : "memory")

#define MBAR_WAIT(mbar, parity) do { \
    uint32_t _m = (uint32_t)(mbar); uint32_t _p = (uint32_t)(parity); uint32_t _d; \
    asm volatile("{\n\t.reg .pred p;\n\t" \
        "mbarrier.try_wait.parity.acquire.cta.shared::cta.b64 p, [%1], %2;\n\t" \
        "selp.b32 %0, 1, 0, p;\n\t}" : "=r"(_d) : "r"(_m), "r"(_p) : "memory"); \
    if (!_d) { \
        asm volatile("{\n\t.reg .pred P1;\n\t" \
            "WL_%=:\n\t" \
            "mbarrier.try_wait.parity.acquire.cta.shared::cta.b64 P1, [%0], %1, 0x989680;\n\t" \
            "@P1 bra.uni WD_%=;\n\t" \
            "bra.uni WL_%=;\n\t" \
            "WD_%=:\n\t}" :: "r"(_m), "r"(_p) : "memory"); \
    } \
} while (0)

__device__ __forceinline__ void bulk_cp(uint32_t dst, const void* src,
                                        uint32_t bytes, uint32_t mbar) {
    asm volatile(
        "cp.async.bulk.shared::cluster.global.mbarrier::complete_tx::bytes "
        "[%0], [%1], %2, [%3];"
        :: "r"(dst), "l"(src), "r"(bytes), "r"(mbar) : "memory");
}

__device__ __forceinline__ void ldsm_x4(uint32_t* r, uint32_t addr) {
    asm volatile("ldmatrix.sync.aligned.m8n8.x4.shared.b16 {%0,%1,%2,%3}, [%4];"
                 : "=r"(r[0]), "=r"(r[1]), "=r"(r[2]), "=r"(r[3]) : "r"(addr));
}

__device__ __forceinline__ void mma16(float* d, const uint32_t* a,
                                      uint32_t b0, uint32_t b1) {
    asm volatile(
        "mma.sync.aligned.m16n8k16.row.col.f32.f16.f16.f32 "
        "{%0,%1,%2,%3}, {%4,%5,%6,%7}, {%8,%9}, {%0,%1,%2,%3};"
        : "+f"(d[0]), "+f"(d[1]), "+f"(d[2]), "+f"(d[3])
        : "r"(a[0]), "r"(a[1]), "r"(a[2]), "r"(a[3]), "r"(b0), "r"(b1));
}

struct GemmArgs {
    const __half* A;      // [M, KA] row-major, lda (halves)
    const __half* A2;     // [M, K-KA] row-major, lda (concat tail)
    const __half* Bt;     // [N, K] row-major, ldb  (B transposed)
    const float*  bias;   // [N] or null
    float*        C;      // f32 out (omode 0/1)
    __half*       Ch;     // f16 out (omode 2)
};

// ---------------------------------------------------------------------------
// fp16 mma.sync GEMM, 64x64 CTA tile, 256 threads (8 warps: 2M x 4N).
// K staged by KS via cp.async.bulk + mbarrier; ldmatrix.x4 fragments.
// omode 0: C[r*ldc+c] f32; 1: [T,B,D] scatter f32; 2: Ch[r*ldc+c] f16.
// ---------------------------------------------------------------------------
__global__ void __launch_bounds__(256, 1) gemm_f16(
    GemmArgs ga0, GemmArgs ga1, int lda, int KA, int ldb, int ldc,
    int omode, int M, int K, int KS, int bufs)
{
    extern __shared__ __half sh[];
    __shared__ uint64_t mbars[2];

    const GemmArgs g = blockIdx.z ? ga1 : ga0;
    const int tid = threadIdx.x, warp = tid >> 5, lane = tid & 31;
    const int q = lane >> 2, r = lane & 3;
    const int wm = warp >> 2;                  // 0..1 : M offset 32*wm
    const int wn = warp & 3;                   // 0..3 : N offset 16*wn
    const int row0 = blockIdx.y * 64;
    const int col0 = blockIdx.x * 64;
    const int RS = KS + 8;                     // halves per smem row
    const int ns = K / KS;
    const uint32_t shb = smem_u32(sh);
    const uint32_t mb  = smem_u32(mbars);
    const uint32_t boff = (uint32_t)bufs * 64u * (uint32_t)RS;   // halves

    if (tid < 2) MBAR_INIT(mb + tid * 8, 1);
    __syncthreads();

    const int  lrow  = tid & 63;
    const bool isA   = tid < 64;
    const bool isLd  = tid < 128;
    const int  arow_g = row0 + lrow;
    const int  arow_c = (arow_g < M) ? arow_g : (M - 1);
    const uint32_t stage_bytes = (uint32_t)KS * 2u * 128u;

    auto issue = [&](int c) {
        const int bi = c & (bufs - 1);
        const uint32_t mbar = mb + (uint32_t)(c & 1) * 8u;
        if (tid == 0)
            asm volatile("mbarrier.arrive.expect_tx.shared.b64 _, [%0], %1;"
                         :: "r"(mbar), "r"(stage_bytes) : "memory");
        if (isLd) {
            const int k0 = c * KS;
            const __half* src;
            uint32_t dst;
            if (isA) {
                const __half* Ab = (k0 < KA) ? g.A : g.A2;
                const int kk = (k0 < KA) ? k0 : (k0 - KA);
                src = Ab + (size_t)arow_c * lda + kk;
                dst = shb + (uint32_t)((bi * 64 + lrow) * RS) * 2u;
            } else {
                src = g.Bt + (size_t)(col0 + lrow) * ldb + (size_t)c * KS;
                dst = shb + (boff + (uint32_t)((bi * 64 + lrow) * RS)) * 2u;
            }
            bulk_cp(dst, src, (uint32_t)KS * 2u, mbar);
        }
    };

    float acc[2][2][4];
    #pragma unroll
    for (int i = 0; i < 2; ++i)
        #pragma unroll
        for (int j2 = 0; j2 < 2; ++j2)
            #pragma unroll
            for (int k2 = 0; k2 < 4; ++k2) acc[i][j2][k2] = 0.f;

    int ph0 = 0, ph1 = 0;
    issue(0);

    const int j   = lane & 7;
    const int sm8 = (lane >> 3) & 1;
    const int sk8 = (lane >> 4) & 1;

    for (int c = 0; c < ns; ++c) {
        if (c + 1 < ns) issue(c + 1);
        if ((c & 1) == 0) { MBAR_WAIT(mb,     ph0); ph0 ^= 1; }
        else              { MBAR_WAIT(mb + 8, ph1); ph1 ^= 1; }

        const int bi = c & (bufs - 1);
        const uint32_t Ab = shb + (uint32_t)(bi * 64 * RS) * 2u;
        const uint32_t Bb = shb + (boff + (uint32_t)(bi * 64 * RS)) * 2u;
        const int steps = KS >> 4;

        const uint32_t arow_off = (uint32_t)((wm * 32 + j + 8 * sm8) * RS + 8 * sk8) * 2u;
        const uint32_t brow_off = (uint32_t)((wn * 16 + j + 8 * sm8) * RS + 8 * sk8) * 2u;

        for (int s = 0; s < steps; ++s) {
            const uint32_t kb2 = (uint32_t)(s * 16) * 2u;
            uint32_t a0[4], a1[4], bb[4];
            ldsm_x4(a0, Ab + arow_off + kb2);
            ldsm_x4(a1, Ab + arow_off + kb2 + (uint32_t)(16 * RS) * 2u);
            ldsm_x4(bb, Bb + brow_off + kb2);
            mma16(acc[0][0], a0, bb[0], bb[2]);
            mma16(acc[0][1], a0, bb[1], bb[3]);
            mma16(acc[1][0], a1, bb[0], bb[2]);
            mma16(acc[1][1], a1, bb[1], bb[3]);
        }
        __syncthreads();
    }

    // ---- epilogue ----
    float bv[2][2];
    #pragma unroll
    for (int nt = 0; nt < 2; ++nt) {
        const int cc = col0 + wn * 16 + nt * 8 + r * 2;
        bv[nt][0] = g.bias ? __ldg(g.bias + cc)     : 0.f;
        bv[nt][1] = g.bias ? __ldg(g.bias + cc + 1) : 0.f;
    }
    #pragma unroll
    for (int mt = 0; mt < 2; ++mt) {
        #pragma unroll
        for (int rh = 0; rh < 2; ++rh) {
            const int rr = row0 + wm * 32 + mt * 16 + rh * 8 + q;
            if (rr >= M) continue;
            #pragma unroll
            for (int nt = 0; nt < 2; ++nt) {
                const int cc = col0 + wn * 16 + nt * 8 + r * 2;
                const float ox = acc[mt][nt][rh * 2 + 0] + bv[nt][0];
                const float oy = acc[mt][nt][rh * 2 + 1] + bv[nt][1];
                if (omode == 2) {
                    __half2* dp = (__half2*)(g.Ch + (size_t)rr * ldc + cc);
                    *dp = __floats2half2_rn(ox, oy);
                } else {
                    float* rowp;
                    if (omode == 0) rowp = g.C + (size_t)rr * ldc;
                    else {
                        const int t = rr % S_, bbn = rr / S_;
                        rowp = g.C + (size_t)t * (B_ * D_) + (size_t)bbn * D_;
                    }
                    *(float2*)(rowp + cc) = make_float2(ox, oy);
                }
            }
        }
    }
}

// ---------------------------------------------------------------------------
// Fused prep: blockIdx.z selects job.
//  z=0..4: transpose+convert (Wq, Wc, Wout, mem b0, mem b1)
//  z=5:    f32->f16 convert of input & memory
// grid (16, 32, 6), 256 threads.
// ---------------------------------------------------------------------------
__global__ void prep_kernel(
    const float* __restrict__ input, const float* __restrict__ memory,
    const float* __restrict__ Wq, const float* __restrict__ Wc,
    const float* __restrict__ Wout,
    __half* __restrict__ in_h, __half* __restrict__ mem_h,
    __half* __restrict__ WqT, __half* __restrict__ WcT,
    __half* __restrict__ WoutT, __half* __restrict__ memT)
{
    const int z = blockIdx.z;
    const int tid = threadIdx.x;

    if (z == 5) {   // conv job
        const int i = (blockIdx.y * 16 + blockIdx.x) * 256 + tid;
        const int n4 = ROWS * D_ / 4;
        if (i < n4) {
            float4 v = ((const float4*)input)[i];
            ((__half2*)in_h)[2 * i]     = __floats2half2_rn(v.x, v.y);
            ((__half2*)in_h)[2 * i + 1] = __floats2half2_rn(v.z, v.w);
            v = ((const float4*)memory)[i];
            ((__half2*)mem_h)[2 * i]     = __floats2half2_rn(v.x, v.y);
            ((__half2*)mem_h)[2 * i + 1] = __floats2half2_rn(v.z, v.w);
        }
        return;
    }

    const float* I; __half* O; int R; int ylim;
    switch (z) {
        case 0: I = Wq;   O = WqT;   R = 512;  ylim = 16; break;
        case 1: I = Wc;   O = WcT;   R = 512;  ylim = 16; break;
        case 2: I = Wout; O = WoutT; R = 1024; ylim = 32; break;
        case 3: I = memory;            O = memT;            R = 400; ylim = 13; break;
        default:I = memory + 400 * 512; O = memT + 512 * 400; R = 400; ylim = 13; break;
    }
    if ((int)blockIdx.y >= ylim) return;
    const int C = 512;

    __shared__ float t[32][33];
    const int c0 = blockIdx.x * 32, r0 = blockIdx.y * 32;
    const int x = tid & 31, y = tid >> 5;    // 32 x 8
    #pragma unroll
    for (int d = 0; d < 32; d += 8) {
        const int rr = r0 + y + d, cc = c0 + x;
        t[y + d][x] = (rr < R && cc < C) ? I[(size_t)rr * C + cc] : 0.f;
    }
    __syncthreads();
    #pragma unroll
    for (int d = 0; d < 32; d += 8) {
        const int orow = c0 + y + d;   // original col
        const int ocol = r0 + x;       // original row
        if (orow < C && ocol < R)
            O[(size_t)orow * R + ocol] = __float2half(t[x][y + d]);
    }
}

// ---------------------------------------------------------------------------
// Scores (f16x2): score[b,t,s] = sum_e v[e] * tanh(wq[b,t,e] + uh[b,s,e])
// q/u in fp16; HADD2 + tanh.approx.f16x2 halves MUFU count; accumulate f32.
// CTA: 8 t-rows x 32 s-cols (warp = 4 s-cols). grid (13, 50, 2), 256 thr.
// Len-aware skipping as in R9.
// ---------------------------------------------------------------------------
__global__ void __launch_bounds__(256) scores_kernel(
    const __half2* __restrict__ wq, const __half2* __restrict__ uh,
    const float* __restrict__ v, const int* __restrict__ lens,
    float* __restrict__ scores)
{
    const int b = blockIdx.z, t0 = blockIdx.y * 8;
    const int sbase = blockIdx.x * 32;
    const int len = lens[b];
    if (sbase >= len) return;                 // uniform across block

    __shared__ __half2 qsm[8][D_ / 2];        // 8 x 256 half2
    __shared__ float2  vsm[D_ / 2];
    const int tid = threadIdx.x;
    for (int i = tid; i < 8 * (D_ / 2); i += 256)
        qsm[i >> 8][i & 255] = wq[((size_t)(b * S_ + t0 + (i >> 8))) * (D_ / 2) + (i & 255)];
    for (int i = tid; i < D_ / 2; i += 256)
        vsm[i] = make_float2(v[2 * i], v[2 * i + 1]);
    __syncthreads();

    const int warp = tid >> 5, lane = tid & 31;
    const int s0 = sbase + warp * 4;
    if (s0 >= len) return;                    // warp-level skip (no syncs below)

    const __half2* up[4];
    #pragma unroll
    for (int j = 0; j < 4; ++j) {
        int sj = s0 + j; if (sj > S_ - 1) sj = S_ - 1;   // clamp (discard at store)
        up[j] = uh + ((size_t)b * S_ + sj) * (D_ / 2);
    }
    float acc[8][4];
    #pragma unroll
    for (int t = 0; t < 8; ++t)
        #pragma unroll
        for (int j = 0; j < 4; ++j) acc[t][j] = 0.f;

    for (int i = 0; i < 8; ++i) {
        const int e2 = i * 32 + lane;
        const float2 vv = vsm[e2];
        __half2 q2[8];
        #pragma unroll
        for (int t = 0; t < 8; ++t) q2[t] = qsm[t][e2];
        #pragma unroll
        for (int j = 0; j < 4; ++j) {
            const __half2 u2 = __ldg(up[j] + e2);
            #pragma unroll
            for (int t = 0; t < 8; ++t) {
                const __half2 th = tanh2_fast(__hadd2(q2[t], u2));
                const float2 f = __half22float2(th);
                acc[t][j] = fmaf(vv.x, f.x, acc[t][j]);
                acc[t][j] = fmaf(vv.y, f.y, acc[t][j]);
            }
        }
    }
    #pragma unroll
    for (int t = 0; t < 8; ++t)
        #pragma unroll
        for (int j = 0; j < 4; ++j) {
            float a = acc[t][j];
            a += __shfl_xor_sync(0xffffffffu, a, 16);
            a += __shfl_xor_sync(0xffffffffu, a, 8);
            a += __shfl_xor_sync(0xffffffffu, a, 4);
            a += __shfl_xor_sync(0xffffffffu, a, 2);
            a += __shfl_xor_sync(0xffffffffu, a, 1);
            if (lane == t * 4 + j && s0 + j < S_)
                scores[((size_t)(b * S_ + t0 + t)) * S_ + s0 + j] = a;
        }
}

// ---------------------------------------------------------------------------
// Masked softmax; writes align f32 to d_out [t,B,S] and f16 copy for ctx gemm.
// ---------------------------------------------------------------------------
__global__ void softmax_kernel(const float* __restrict__ scores, const int* __restrict__ lens,
                               float* __restrict__ align_out, __half* __restrict__ align_h)
{
    const int t = blockIdx.x;
    const int b = blockIdx.y;
    const int len = lens[b];
    const int tid = threadIdx.x;   // 128

    __shared__ float sm[S_];
    __shared__ float red[4];

    const float* srow = scores + ((size_t)(b * S_ + t)) * S_;

    float mx = -1e30f;
    for (int s = tid; s < S_; s += 128) {
        const bool ok = (s < len) && (s != t);
        const float val = ok ? srow[s] : -1e30f;
        sm[s] = val;
        mx = fmaxf(mx, val);
    }
    #pragma unroll
    for (int o = 16; o; o >>= 1) mx = fmaxf(mx, __shfl_xor_sync(0xffffffffu, mx, o));
    if ((tid & 31) == 0) red[tid >> 5] = mx;
    __syncthreads();
    const float bm = fmaxf(fmaxf(red[0], red[1]), fmaxf(red[2], red[3]));
    __syncthreads();

    float sum = 0.0f;
    for (int s = tid; s < S_; s += 128) {
        const float val = sm[s];
        const float e = (val > -1e29f) ? __expf(val - bm) : 0.0f;
        sm[s] = e;
        sum += e;
    }
    #pragma unroll
    for (int o = 16; o; o >>= 1) sum += __shfl_xor_sync(0xffffffffu, sum, o);
    if ((tid & 31) == 0) red[tid >> 5] = sum;
    __syncthreads();
    const float inv = 1.0f / (red[0] + red[1] + red[2] + red[3]);

    for (int s = tid; s < S_; s += 128) {
        const float a = sm[s] * inv;
        align_out[(size_t)t * (B_ * S_) + (size_t)b * S_ + s] = a;
        align_h[(size_t)t * (B_ * S_) + (size_t)b * S_ + s]   = __float2half(a);
    }
}

// ---------------------------------------------------------------------------
extern "C" void kernel_launch(void* const* d_in, const int* in_sizes, int n_in,
                              void* d_out, int out_size)
{
    const float* input  = (const float*)d_in[0];
    const float* memory = (const float*)d_in[1];
    const int*   lens   = (const int*)d_in[2];
    const float* Wq     = (const float*)d_in[3];
    const float* bq     = (const float*)d_in[4];
    const float* Wc     = (const float*)d_in[5];
    const float* v      = (const float*)d_in[6];
    const float* Wout   = (const float*)d_in[7];
    const float* bout   = (const float*)d_in[8];
    float* out = (float*)d_out;

    float *sc_p;
    __half *wq_h, *uh_h, *in_h, *mem_h, *memT_h, *WqT, *WcT, *WoutT, *ctx_h, *align_h;
    cudaGetSymbolAddress((void**)&sc_p,    g_scores);
    cudaGetSymbolAddress((void**)&wq_h,    g_wq_h);
    cudaGetSymbolAddress((void**)&uh_h,    g_uh_h);
    cudaGetSymbolAddress((void**)&in_h,    g_in_h);
    cudaGetSymbolAddress((void**)&mem_h,   g_mem_h);
    cudaGetSymbolAddress((void**)&memT_h,  g_memT_h);
    cudaGetSymbolAddress((void**)&WqT,     g_WqT);
    cudaGetSymbolAddress((void**)&WcT,     g_WcT);
    cudaGetSymbolAddress((void**)&WoutT,   g_WoutT);
    cudaGetSymbolAddress((void**)&ctx_h,   g_ctx_h);
    cudaGetSymbolAddress((void**)&align_h, g_align_h);

    static bool attr_set = false;
    if (!attr_set) {
        cudaFuncSetAttribute(gemm_f16, cudaFuncAttributeMaxDynamicSharedMemorySize,
                             2 * 2 * 64 * (256 + 8) * 2);   // 135168
        attr_set = true;
    }

    // ---- prep (fused: 4 transposes + f32->f16 conversions) ----
    prep_kernel<<<dim3(16, 32, 6), 256>>>(
        input, memory, Wq, Wc, Wout, in_h, mem_h, WqT, WcT, WoutT, memT_h);

    // ---- 1) fused: z=0 -> wq_h = input@Wq + bq; z=1 -> uh_h = memory@Wc (f16 out)
    {
        GemmArgs gq{in_h,  in_h,  WqT, bq,      nullptr, wq_h};
        GemmArgs gu{mem_h, mem_h, WcT, nullptr, nullptr, uh_h};
        gemm_f16<<<dim3(8, 13, 2), 256, 2 * 2 * 64 * 264 * 2>>>(
            gq, gu, 512, 512, 512, 512, 2, 800, 512, 256, 2);
    }
    // ---- 2) scores (len-aware, f16x2 tanh) ----
    scores_kernel<<<dim3(13, 50, 2), 256>>>(
        (const __half2*)wq_h, (const __half2*)uh_h, v, lens, sc_p);
    // ---- 3) masked softmax -> align (f32 in d_out, f16 copy) ----
    softmax_kernel<<<dim3(400, 2), 128>>>(sc_p, lens, out + ALIGN_OFF, align_h);
    // ---- 4) context: c[b] = align[b] @ memory[b] -> ctx_h (f16) ----
    {
        GemmArgs c0{align_h,       align_h,       memT_h,             nullptr, nullptr, ctx_h};
        GemmArgs c1{align_h + S_,  align_h + S_,  memT_h + D_ * S_,   nullptr, nullptr, ctx_h + S_ * D_};
        gemm_f16<<<dim3(8, 7, 2), 256, 1 * 2 * 64 * 408 * 2>>>(
            c0, c1, 800, 400, 400, 512, 2, 400, 400, 400, 1);
    }
    // ---- 5) attn_h = [ctx | input] @ Wout + bout -> [T,B,D] in d_out ----
    {
        GemmArgs go{ctx_h, in_h, WoutT, bout, out, nullptr};
        gemm_f16<<<dim3(8, 13, 1), 256, 2 * 2 * 64 * 264 * 2>>>(
            go, go, 512, 512, 1024, 512, 1, 800, 1024, 256, 2);
    }
}

// round 11
// speedup vs baseline: 1.9223x; 1.0875x over previous
#include <cuda_runtime.h>
#include <cuda_fp16.h>
#include <cstdint>
#include <cstddef>

// Problem constants
#define B_  2
#define S_  400
#define D_  512
#define ROWS (B_ * S_)                  // 800
#define ALIGN_OFF (S_ * B_ * D_)        // 409600

// Scratch (device globals: no allocation allowed)
__device__ float  g_scores[ROWS * S_];
__device__ __half g_wq_h[ROWS * D_];
__device__ __half g_uh_h[ROWS * D_];
__device__ __half g_in_h[ROWS * D_];
__device__ __half g_mem_h[ROWS * D_];
__device__ __half g_memT_h[B_ * D_ * S_];      // per b: [512][400]
__device__ __half g_WqT[D_ * D_];              // [n][k]
__device__ __half g_WcT[D_ * D_];
__device__ __half g_WoutT[D_ * 2 * D_];        // [512][1024]
__device__ __half g_ctx_h[ROWS * D_];
__device__ __half g_align_h[S_ * B_ * S_];     // [t][b][s]

// ---------------------------------------------------------------------------
__device__ __forceinline__ __half2 tanh2_fast(__half2 x) {
    uint32_t xi = *(uint32_t*)&x, yi;
    asm("tanh.approx.f16x2 %0, %1;" : "=r"(yi) : "r"(xi));
    return *(__half2*)&yi;
}

__device__ __forceinline__ uint32_t smem_u32(const void* p) {
    uint32_t a;
    asm("{ .reg .u64 t; cvta.to.shared.u64 t, %1; cvt.u32.u64 %0, t; }"
        : "=r"(a) : "l"(p));
    return a;
}

#define MBAR_INIT(mbar, cnt) \
    asm volatile("mbarrier.init.shared.b64 [%0], %1;" \
        :: "r"((uint32_t)(mbar)), "r"((uint32_t)(cnt)) : "memory")

#define MBAR_WAIT(mbar, parity) do { \
    uint32_t _m = (uint32_t)(mbar); uint32_t _p = (uint32_t)(parity); uint32_t _d; \
    asm volatile("{\n\t.reg .pred p;\n\t" \
        "mbarrier.try_wait.parity.acquire.cta.shared::cta.b64 p, [%1], %2;\n\t" \
        "selp.b32 %0, 1, 0, p;\n\t}" : "=r"(_d) : "r"(_m), "r"(_p) : "memory"); \
    if (!_d) { \
        asm volatile("{\n\t.reg .pred P1;\n\t" \
            "WL_%=:\n\t" \
            "mbarrier.try_wait.parity.acquire.cta.shared::cta.b64 P1, [%0], %1, 0x989680;\n\t" \
            "@P1 bra.uni WD_%=;\n\t" \
            "bra.uni WL_%=;\n\t" \
            "WD_%=:\n\t}" :: "r"(_m), "r"(_p) : "memory"); \
    } \
} while (0)

__device__ __forceinline__ void bulk_cp(uint32_t dst, const void* src,
                                        uint32_t bytes, uint32_t mbar) {
    asm volatile(
        "cp.async.bulk.shared::cluster.global.mbarrier::complete_tx::bytes "
        "[%0], [%1], %2, [%3];"
        :: "r"(dst), "l"(src), "r"(bytes), "r"(mbar) : "memory");
}

__device__ __forceinline__ void ldsm_x4(uint32_t* r, uint32_t addr) {
    asm volatile("ldmatrix.sync.aligned.m8n8.x4.shared.b16 {%0,%1,%2,%3}, [%4];"
                 : "=r"(r[0]), "=r"(r[1]), "=r"(r[2]), "=r"(r[3]) : "r"(addr));
}

__device__ __forceinline__ void mma16(float* d, const uint32_t* a,
                                      uint32_t b0, uint32_t b1) {
    asm volatile(
        "mma.sync.aligned.m16n8k16.row.col.f32.f16.f16.f32 "
        "{%0,%1,%2,%3}, {%4,%5,%6,%7}, {%8,%9}, {%0,%1,%2,%3};"
        : "+f"(d[0]), "+f"(d[1]), "+f"(d[2]), "+f"(d[3])
        : "r"(a[0]), "r"(a[1]), "r"(a[2]), "r"(a[3]), "r"(b0), "r"(b1));
}

struct GemmArgs {
    const __half* A;      // [M, KA] row-major, lda (halves)
    const __half* A2;     // [M, K-KA] row-major, lda (concat tail)
    const __half* Bt;     // [N, K] row-major, ldb  (B transposed)
    const float*  bias;   // [N] or null
    float*        C;      // f32 out (omode 0/1)
    __half*       Ch;     // f16 out (omode 2)
};

// ---------------------------------------------------------------------------
// fp16 mma.sync GEMM, 64x64 CTA tile, 256 threads (8 warps: 2M x 4N).
// K staged by KS via cp.async.bulk + mbarrier; ldmatrix.x4 fragments.
// omode 0: C[r*ldc+c] f32; 1: [T,B,D] scatter f32; 2: Ch[r*ldc+c] f16.
// ---------------------------------------------------------------------------
__global__ void __launch_bounds__(256, 1) gemm_f16(
    GemmArgs ga0, GemmArgs ga1, int lda, int KA, int ldb, int ldc,
    int omode, int M, int K, int KS, int bufs)
{
    extern __shared__ __half sh[];
    __shared__ uint64_t mbars[2];

    const GemmArgs g = blockIdx.z ? ga1 : ga0;
    const int tid = threadIdx.x, warp = tid >> 5, lane = tid & 31;
    const int q = lane >> 2, r = lane & 3;
    const int wm = warp >> 2;                  // 0..1 : M offset 32*wm
    const int wn = warp & 3;                   // 0..3 : N offset 16*wn
    const int row0 = blockIdx.y * 64;
    const int col0 = blockIdx.x * 64;
    const int RS = KS + 8;                     // halves per smem row
    const int ns = K / KS;
    const uint32_t shb = smem_u32(sh);
    const uint32_t mb  = smem_u32(mbars);
    const uint32_t boff = (uint32_t)bufs * 64u * (uint32_t)RS;   // halves

    if (tid < 2) MBAR_INIT(mb + tid * 8, 1);
    __syncthreads();

    const int  lrow  = tid & 63;
    const bool isA   = tid < 64;
    const bool isLd  = tid < 128;
    const int  arow_g = row0 + lrow;
    const int  arow_c = (arow_g < M) ? arow_g : (M - 1);
    const uint32_t stage_bytes = (uint32_t)KS * 2u * 128u;

    auto issue = [&](int c) {
        const int bi = c & (bufs - 1);
        const uint32_t mbar = mb + (uint32_t)(c & 1) * 8u;
        if (tid == 0)
            asm volatile("mbarrier.arrive.expect_tx.shared.b64 _, [%0], %1;"
                         :: "r"(mbar), "r"(stage_bytes) : "memory");
        if (isLd) {
            const int k0 = c * KS;
            const __half* src;
            uint32_t dst;
            if (isA) {
                const __half* Ab = (k0 < KA) ? g.A : g.A2;
                const int kk = (k0 < KA) ? k0 : (k0 - KA);
                src = Ab + (size_t)arow_c * lda + kk;
                dst = shb + (uint32_t)((bi * 64 + lrow) * RS) * 2u;
            } else {
                src = g.Bt + (size_t)(col0 + lrow) * ldb + (size_t)c * KS;
                dst = shb + (boff + (uint32_t)((bi * 64 + lrow) * RS)) * 2u;
            }
            bulk_cp(dst, src, (uint32_t)KS * 2u, mbar);
        }
    };

    float acc[2][2][4];
    #pragma unroll
    for (int i = 0; i < 2; ++i)
        #pragma unroll
        for (int j2 = 0; j2 < 2; ++j2)
            #pragma unroll
            for (int k2 = 0; k2 < 4; ++k2) acc[i][j2][k2] = 0.f;

    int ph0 = 0, ph1 = 0;
    issue(0);

    const int j   = lane & 7;
    const int sm8 = (lane >> 3) & 1;
    const int sk8 = (lane >> 4) & 1;

    for (int c = 0; c < ns; ++c) {
        if (c + 1 < ns) issue(c + 1);
        if ((c & 1) == 0) { MBAR_WAIT(mb,     ph0); ph0 ^= 1; }
        else              { MBAR_WAIT(mb + 8, ph1); ph1 ^= 1; }

        const int bi = c & (bufs - 1);
        const uint32_t Ab = shb + (uint32_t)(bi * 64 * RS) * 2u;
        const uint32_t Bb = shb + (boff + (uint32_t)(bi * 64 * RS)) * 2u;
        const int steps = KS >> 4;

        const uint32_t arow_off = (uint32_t)((wm * 32 + j + 8 * sm8) * RS + 8 * sk8) * 2u;
        const uint32_t brow_off = (uint32_t)((wn * 16 + j + 8 * sm8) * RS + 8 * sk8) * 2u;

        for (int s = 0; s < steps; ++s) {
            const uint32_t kb2 = (uint32_t)(s * 16) * 2u;
            uint32_t a0[4], a1[4], bb[4];
            ldsm_x4(a0, Ab + arow_off + kb2);
            ldsm_x4(a1, Ab + arow_off + kb2 + (uint32_t)(16 * RS) * 2u);
            ldsm_x4(bb, Bb + brow_off + kb2);
            mma16(acc[0][0], a0, bb[0], bb[2]);
            mma16(acc[0][1], a0, bb[1], bb[3]);
            mma16(acc[1][0], a1, bb[0], bb[2]);
            mma16(acc[1][1], a1, bb[1], bb[3]);
        }
        __syncthreads();
    }

    // ---- epilogue ----
    float bv[2][2];
    #pragma unroll
    for (int nt = 0; nt < 2; ++nt) {
        const int cc = col0 + wn * 16 + nt * 8 + r * 2;
        bv[nt][0] = g.bias ? __ldg(g.bias + cc)     : 0.f;
        bv[nt][1] = g.bias ? __ldg(g.bias + cc + 1) : 0.f;
    }
    #pragma unroll
    for (int mt = 0; mt < 2; ++mt) {
        #pragma unroll
        for (int rh = 0; rh < 2; ++rh) {
            const int rr = row0 + wm * 32 + mt * 16 + rh * 8 + q;
            if (rr >= M) continue;
            #pragma unroll
            for (int nt = 0; nt < 2; ++nt) {
                const int cc = col0 + wn * 16 + nt * 8 + r * 2;
                const float ox = acc[mt][nt][rh * 2 + 0] + bv[nt][0];
                const float oy = acc[mt][nt][rh * 2 + 1] + bv[nt][1];
                if (omode == 2) {
                    __half2* dp = (__half2*)(g.Ch + (size_t)rr * ldc + cc);
                    *dp = __floats2half2_rn(ox, oy);
                } else {
                    float* rowp;
                    if (omode == 0) rowp = g.C + (size_t)rr * ldc;
                    else {
                        const int t = rr % S_, bbn = rr / S_;
                        rowp = g.C + (size_t)t * (B_ * D_) + (size_t)bbn * D_;
                    }
                    *(float2*)(rowp + cc) = make_float2(ox, oy);
                }
            }
        }
    }
}

// ---------------------------------------------------------------------------
// Fused prep: blockIdx.z selects job.
//  z=0..4: transpose+convert (Wq, Wc, Wout, mem b0, mem b1)
//  z=5:    f32->f16 convert of input & memory
// grid (16, 32, 6), 256 threads.
// ---------------------------------------------------------------------------
__global__ void prep_kernel(
    const float* __restrict__ input, const float* __restrict__ memory,
    const float* __restrict__ Wq, const float* __restrict__ Wc,
    const float* __restrict__ Wout,
    __half* __restrict__ in_h, __half* __restrict__ mem_h,
    __half* __restrict__ WqT, __half* __restrict__ WcT,
    __half* __restrict__ WoutT, __half* __restrict__ memT)
{
    const int z = blockIdx.z;
    const int tid = threadIdx.x;

    if (z == 5) {   // conv job
        const int i = (blockIdx.y * 16 + blockIdx.x) * 256 + tid;
        const int n4 = ROWS * D_ / 4;
        if (i < n4) {
            float4 v = ((const float4*)input)[i];
            ((__half2*)in_h)[2 * i]     = __floats2half2_rn(v.x, v.y);
            ((__half2*)in_h)[2 * i + 1] = __floats2half2_rn(v.z, v.w);
            v = ((const float4*)memory)[i];
            ((__half2*)mem_h)[2 * i]     = __floats2half2_rn(v.x, v.y);
            ((__half2*)mem_h)[2 * i + 1] = __floats2half2_rn(v.z, v.w);
        }
        return;
    }

    const float* I; __half* O; int R; int ylim;
    switch (z) {
        case 0: I = Wq;   O = WqT;   R = 512;  ylim = 16; break;
        case 1: I = Wc;   O = WcT;   R = 512;  ylim = 16; break;
        case 2: I = Wout; O = WoutT; R = 1024; ylim = 32; break;
        case 3: I = memory;            O = memT;            R = 400; ylim = 13; break;
        default:I = memory + 400 * 512; O = memT + 512 * 400; R = 400; ylim = 13; break;
    }
    if ((int)blockIdx.y >= ylim) return;
    const int C = 512;

    __shared__ float t[32][33];
    const int c0 = blockIdx.x * 32, r0 = blockIdx.y * 32;
    const int x = tid & 31, y = tid >> 5;    // 32 x 8
    #pragma unroll
    for (int d = 0; d < 32; d += 8) {
        const int rr = r0 + y + d, cc = c0 + x;
        t[y + d][x] = (rr < R && cc < C) ? I[(size_t)rr * C + cc] : 0.f;
    }
    __syncthreads();
    #pragma unroll
    for (int d = 0; d < 32; d += 8) {
        const int orow = c0 + y + d;   // original col
        const int ocol = r0 + x;       // original row
        if (orow < C && ocol < R)
            O[(size_t)orow * R + ocol] = __float2half(t[x][y + d]);
    }
}

// ---------------------------------------------------------------------------
// Scores (f16x2 + HFMA2 local accumulation): minimal issue count:
// HADD2 + tanh.approx.f16x2 + HFMA2 per 2 elements; half2 accumulators
// flushed to f32 every 4 k-iterations (8 elems/lane-half) to bound fp16
// rounding. CTA: 8 t x 32 s; grid (13, 50, 2), 256 thr. Len-aware skips.
// ---------------------------------------------------------------------------
__global__ void __launch_bounds__(256) scores_kernel(
    const __half2* __restrict__ wq, const __half2* __restrict__ uh,
    const float* __restrict__ v, const int* __restrict__ lens,
    float* __restrict__ scores)
{
    const int b = blockIdx.z, t0 = blockIdx.y * 8;
    const int sbase = blockIdx.x * 32;
    const int len = lens[b];
    if (sbase >= len) return;                 // uniform across block

    __shared__ __half2 qsm[8][D_ / 2];        // 8 x 256 half2
    __shared__ __half2 vsm[D_ / 2];
    const int tid = threadIdx.x;
    for (int i = tid; i < 8 * (D_ / 2); i += 256)
        qsm[i >> 8][i & 255] = wq[((size_t)(b * S_ + t0 + (i >> 8))) * (D_ / 2) + (i & 255)];
    for (int i = tid; i < D_ / 2; i += 256)
        vsm[i] = __floats2half2_rn(v[2 * i], v[2 * i + 1]);
    __syncthreads();

    const int warp = tid >> 5, lane = tid & 31;
    const int s0 = sbase + warp * 4;
    if (s0 >= len) return;                    // warp-level skip (no syncs below)

    const __half2* up[4];
    #pragma unroll
    for (int j = 0; j < 4; ++j) {
        int sj = s0 + j; if (sj > S_ - 1) sj = S_ - 1;   // clamp (discard at store)
        up[j] = uh + ((size_t)b * S_ + sj) * (D_ / 2);
    }
    float acc[8][4];
    __half2 acc2[8][4];
    const __half2 h2z = __floats2half2_rn(0.f, 0.f);
    #pragma unroll
    for (int t = 0; t < 8; ++t)
        #pragma unroll
        for (int j = 0; j < 4; ++j) { acc[t][j] = 0.f; acc2[t][j] = h2z; }

    #pragma unroll
    for (int i = 0; i < 8; ++i) {
        const int e2 = i * 32 + lane;
        const __half2 v2 = vsm[e2];
        __half2 q2[8];
        #pragma unroll
        for (int t = 0; t < 8; ++t) q2[t] = qsm[t][e2];
        #pragma unroll
        for (int j = 0; j < 4; ++j) {
            const __half2 u2 = __ldg(up[j] + e2);
            #pragma unroll
            for (int t = 0; t < 8; ++t)
                acc2[t][j] = __hfma2(v2, tanh2_fast(__hadd2(q2[t], u2)), acc2[t][j]);
        }
        if ((i & 3) == 3) {   // flush fp16 partials into f32 accumulators
            #pragma unroll
            for (int t = 0; t < 8; ++t)
                #pragma unroll
                for (int j = 0; j < 4; ++j) {
                    const float2 f = __half22float2(acc2[t][j]);
                    acc[t][j] += f.x + f.y;
                    acc2[t][j] = h2z;
                }
        }
    }
    #pragma unroll
    for (int t = 0; t < 8; ++t)
        #pragma unroll
        for (int j = 0; j < 4; ++j) {
            float a = acc[t][j];
            a += __shfl_xor_sync(0xffffffffu, a, 16);
            a += __shfl_xor_sync(0xffffffffu, a, 8);
            a += __shfl_xor_sync(0xffffffffu, a, 4);
            a += __shfl_xor_sync(0xffffffffu, a, 2);
            a += __shfl_xor_sync(0xffffffffu, a, 1);
            if (lane == t * 4 + j && s0 + j < S_)
                scores[((size_t)(b * S_ + t0 + t)) * S_ + s0 + j] = a;
        }
}

// ---------------------------------------------------------------------------
// Masked softmax, warp-per-row: 100 CTAs x 8 warps, values in registers,
// shuffle-only reductions (no smem, no __syncthreads).
// ---------------------------------------------------------------------------
__global__ void __launch_bounds__(256) softmax_kernel(
    const float* __restrict__ scores, const int* __restrict__ lens,
    float* __restrict__ align_out, __half* __restrict__ align_h)
{
    const int rowid = blockIdx.x * 8 + (threadIdx.x >> 5);   // 0..799
    const int lane  = threadIdx.x & 31;
    const int b = rowid / S_;
    const int t = rowid % S_;
    const int len = lens[b];

    const float* srow = scores + ((size_t)(b * S_ + t)) * S_;

    float vals[13];
    float mx = -1e30f;
    #pragma unroll
    for (int k = 0; k < 13; ++k) {
        const int s = k * 32 + lane;
        const bool ok = (s < len) && (s != t);        // len <= S_, so s<S_ implied
        const float val = ok ? __ldg(srow + s) : -1e30f;
        vals[k] = val;
        mx = fmaxf(mx, val);
    }
    #pragma unroll
    for (int o = 16; o; o >>= 1) mx = fmaxf(mx, __shfl_xor_sync(0xffffffffu, mx, o));

    float sum = 0.f;
    #pragma unroll
    for (int k = 0; k < 13; ++k) {
        const float e = (vals[k] > -1e29f) ? __expf(vals[k] - mx) : 0.f;
        vals[k] = e;
        sum += e;
    }
    #pragma unroll
    for (int o = 16; o; o >>= 1) sum += __shfl_xor_sync(0xffffffffu, sum, o);
    const float inv = 1.0f / sum;

    const size_t obase = (size_t)t * (B_ * S_) + (size_t)b * S_;
    #pragma unroll
    for (int k = 0; k < 13; ++k) {
        const int s = k * 32 + lane;
        if (s < S_) {
            const float a = vals[k] * inv;
            align_out[obase + s] = a;
            align_h[obase + s]   = __float2half(a);
        }
    }
}

// ---------------------------------------------------------------------------
extern "C" void kernel_launch(void* const* d_in, const int* in_sizes, int n_in,
                              void* d_out, int out_size)
{
    const float* input  = (const float*)d_in[0];
    const float* memory = (const float*)d_in[1];
    const int*   lens   = (const int*)d_in[2];
    const float* Wq     = (const float*)d_in[3];
    const float* bq     = (const float*)d_in[4];
    const float* Wc     = (const float*)d_in[5];
    const float* v      = (const float*)d_in[6];
    const float* Wout   = (const float*)d_in[7];
    const float* bout   = (const float*)d_in[8];
    float* out = (float*)d_out;

    float *sc_p;
    __half *wq_h, *uh_h, *in_h, *mem_h, *memT_h, *WqT, *WcT, *WoutT, *ctx_h, *align_h;
    cudaGetSymbolAddress((void**)&sc_p,    g_scores);
    cudaGetSymbolAddress((void**)&wq_h,    g_wq_h);
    cudaGetSymbolAddress((void**)&uh_h,    g_uh_h);
    cudaGetSymbolAddress((void**)&in_h,    g_in_h);
    cudaGetSymbolAddress((void**)&mem_h,   g_mem_h);
    cudaGetSymbolAddress((void**)&memT_h,  g_memT_h);
    cudaGetSymbolAddress((void**)&WqT,     g_WqT);
    cudaGetSymbolAddress((void**)&WcT,     g_WcT);
    cudaGetSymbolAddress((void**)&WoutT,   g_WoutT);
    cudaGetSymbolAddress((void**)&ctx_h,   g_ctx_h);
    cudaGetSymbolAddress((void**)&align_h, g_align_h);

    static bool attr_set = false;
    if (!attr_set) {
        cudaFuncSetAttribute(gemm_f16, cudaFuncAttributeMaxDynamicSharedMemorySize,
                             2 * 2 * 64 * (256 + 8) * 2);   // 135168
        attr_set = true;
    }

    // ---- prep (fused: 4 transposes + f32->f16 conversions) ----
    prep_kernel<<<dim3(16, 32, 6), 256>>>(
        input, memory, Wq, Wc, Wout, in_h, mem_h, WqT, WcT, WoutT, memT_h);

    // ---- 1) fused: z=0 -> wq_h = input@Wq + bq; z=1 -> uh_h = memory@Wc (f16 out)
    {
        GemmArgs gq{in_h,  in_h,  WqT, bq,      nullptr, wq_h};
        GemmArgs gu{mem_h, mem_h, WcT, nullptr, nullptr, uh_h};
        gemm_f16<<<dim3(8, 13, 2), 256, 2 * 2 * 64 * 264 * 2>>>(
            gq, gu, 512, 512, 512, 512, 2, 800, 512, 256, 2);
    }
    // ---- 2) scores (len-aware, f16x2 tanh + HFMA2 accumulation) ----
    scores_kernel<<<dim3(13, 50, 2), 256>>>(
        (const __half2*)wq_h, (const __half2*)uh_h, v, lens, sc_p);
    // ---- 3) masked softmax (warp-per-row) -> align (f32 in d_out, f16 copy) ----
    softmax_kernel<<<100, 256>>>(sc_p, lens, out + ALIGN_OFF, align_h);
    // ---- 4) context: c[b] = align[b] @ memory[b] -> ctx_h (f16) ----
    {
        GemmArgs c0{align_h,       align_h,       memT_h,             nullptr, nullptr, ctx_h};
        GemmArgs c1{align_h + S_,  align_h + S_,  memT_h + D_ * S_,   nullptr, nullptr, ctx_h + S_ * D_};
        gemm_f16<<<dim3(8, 7, 2), 256, 1 * 2 * 64 * 408 * 2>>>(
            c0, c1, 800, 400, 400, 512, 2, 400, 400, 400, 1);
    }
    // ---- 5) attn_h = [ctx | input] @ Wout + bout -> [T,B,D] in d_out ----
    {
        GemmArgs go{ctx_h, in_h, WoutT, bout, out, nullptr};
        gemm_f16<<<dim3(8, 13, 1), 256, 2 * 2 * 64 * 264 * 2>>>(
            go, go, 512, 512, 1024, 512, 1, 800, 1024, 256, 2);
    }
}

// round 12
// speedup vs baseline: 1.9963x; 1.0385x over previous
#include <cuda_runtime.h>
#include <cuda_fp16.h>
#include <cstdint>
#include <cstddef>

// Problem constants
#define B_  2
#define S_  400
#define D_  512
#define ROWS (B_ * S_)                  // 800
#define ALIGN_OFF (S_ * B_ * D_)        // 409600

// Scratch (device globals: no allocation allowed)
__device__ __half g_wq_h[ROWS * D_];
__device__ __half g_uh_h[ROWS * D_];
__device__ __half g_in_h[ROWS * D_];
__device__ __half g_mem_h[ROWS * D_];
__device__ __half g_memT_h[B_ * D_ * S_];      // per b: [512][400]
__device__ __half g_WqT[D_ * D_];              // [n][k]
__device__ __half g_WcT[D_ * D_];
__device__ __half g_WoutT[D_ * 2 * D_];        // [512][1024]
__device__ __half g_ctx_h[ROWS * D_];
__device__ __half g_align_h[S_ * B_ * S_];     // [t][b][s]

// ---------------------------------------------------------------------------
__device__ __forceinline__ __half2 tanh2_fast(__half2 x) {
    uint32_t xi = *(uint32_t*)&x, yi;
    asm("tanh.approx.f16x2 %0, %1;" : "=r"(yi) : "r"(xi));
    return *(__half2*)&yi;
}

__device__ __forceinline__ uint32_t smem_u32(const void* p) {
    uint32_t a;
    asm("{ .reg .u64 t; cvta.to.shared.u64 t, %1; cvt.u32.u64 %0, t; }"
        : "=r"(a) : "l"(p));
    return a;
}

#define MBAR_INIT(mbar, cnt) \
    asm volatile("mbarrier.init.shared.b64 [%0], %1;" \
        :: "r"((uint32_t)(mbar)), "r"((uint32_t)(cnt)) : "memory")

#define MBAR_WAIT(mbar, parity) do { \
    uint32_t _m = (uint32_t)(mbar); uint32_t _p = (uint32_t)(parity); uint32_t _d; \
    asm volatile("{\n\t.reg .pred p;\n\t" \
        "mbarrier.try_wait.parity.acquire.cta.shared::cta.b64 p, [%1], %2;\n\t" \
        "selp.b32 %0, 1, 0, p;\n\t}" : "=r"(_d) : "r"(_m), "r"(_p) : "memory"); \
    if (!_d) { \
        asm volatile("{\n\t.reg .pred P1;\n\t" \
            "WL_%=:\n\t" \
            "mbarrier.try_wait.parity.acquire.cta.shared::cta.b64 P1, [%0], %1, 0x989680;\n\t" \
            "@P1 bra.uni WD_%=;\n\t" \
            "bra.uni WL_%=;\n\t" \
            "WD_%=:\n\t}" :: "r"(_m), "r"(_p) : "memory"); \
    } \
} while (0)

__device__ __forceinline__ void bulk_cp(uint32_t dst, const void* src,
                                        uint32_t bytes, uint32_t mbar) {
    asm volatile(
        "cp.async.bulk.shared::cluster.global.mbarrier::complete_tx::bytes "
        "[%0], [%1], %2, [%3];"
        :: "r"(dst), "l"(src), "r"(bytes), "r"(mbar) : "memory");
}

__device__ __forceinline__ void ldsm_x4(uint32_t* r, uint32_t addr) {
    asm volatile("ldmatrix.sync.aligned.m8n8.x4.shared.b16 {%0,%1,%2,%3}, [%4];"
                 : "=r"(r[0]), "=r"(r[1]), "=r"(r[2]), "=r"(r[3]) : "r"(addr));
}

__device__ __forceinline__ void mma16(float* d, const uint32_t* a,
                                      uint32_t b0, uint32_t b1) {
    asm volatile(
        "mma.sync.aligned.m16n8k16.row.col.f32.f16.f16.f32 "
        "{%0,%1,%2,%3}, {%4,%5,%6,%7}, {%8,%9}, {%0,%1,%2,%3};"
        : "+f"(d[0]), "+f"(d[1]), "+f"(d[2]), "+f"(d[3])
        : "r"(a[0]), "r"(a[1]), "r"(a[2]), "r"(a[3]), "r"(b0), "r"(b1));
}

struct GemmArgs {
    const __half* A;      // [M, KA] row-major, lda (halves)
    const __half* A2;     // [M, K-KA] row-major, lda (concat tail)
    const __half* Bt;     // [N, K] row-major, ldb  (B transposed)
    const float*  bias;   // [N] or null
    float*        C;      // f32 out (omode 0/1)
    __half*       Ch;     // f16 out (omode 2)
};

// ---------------------------------------------------------------------------
// fp16 mma.sync GEMM, 64x64 CTA tile, 256 threads (8 warps: 2M x 4N).
// K staged by KS via cp.async.bulk + mbarrier; ldmatrix.x4 fragments.
// omode 0: C[r*ldc+c] f32; 1: [T,B,D] scatter f32; 2: Ch[r*ldc+c] f16.
// ---------------------------------------------------------------------------
__global__ void __launch_bounds__(256, 1) gemm_f16(
    GemmArgs ga0, GemmArgs ga1, int lda, int KA, int ldb, int ldc,
    int omode, int M, int K, int KS, int bufs)
{
    extern __shared__ __half sh[];
    __shared__ uint64_t mbars[2];

    const GemmArgs g = blockIdx.z ? ga1 : ga0;
    const int tid = threadIdx.x, warp = tid >> 5, lane = tid & 31;
    const int q = lane >> 2, r = lane & 3;
    const int wm = warp >> 2;                  // 0..1 : M offset 32*wm
    const int wn = warp & 3;                   // 0..3 : N offset 16*wn
    const int row0 = blockIdx.y * 64;
    const int col0 = blockIdx.x * 64;
    const int RS = KS + 8;                     // halves per smem row
    const int ns = K / KS;
    const uint32_t shb = smem_u32(sh);
    const uint32_t mb  = smem_u32(mbars);
    const uint32_t boff = (uint32_t)bufs * 64u * (uint32_t)RS;   // halves

    if (tid < 2) MBAR_INIT(mb + tid * 8, 1);
    __syncthreads();

    const int  lrow  = tid & 63;
    const bool isA   = tid < 64;
    const bool isLd  = tid < 128;
    const int  arow_g = row0 + lrow;
    const int  arow_c = (arow_g < M) ? arow_g : (M - 1);
    const uint32_t stage_bytes = (uint32_t)KS * 2u * 128u;

    auto issue = [&](int c) {
        const int bi = c & (bufs - 1);
        const uint32_t mbar = mb + (uint32_t)(c & 1) * 8u;
        if (tid == 0)
            asm volatile("mbarrier.arrive.expect_tx.shared.b64 _, [%0], %1;"
                         :: "r"(mbar), "r"(stage_bytes) : "memory");
        if (isLd) {
            const int k0 = c * KS;
            const __half* src;
            uint32_t dst;
            if (isA) {
                const __half* Ab = (k0 < KA) ? g.A : g.A2;
                const int kk = (k0 < KA) ? k0 : (k0 - KA);
                src = Ab + (size_t)arow_c * lda + kk;
                dst = shb + (uint32_t)((bi * 64 + lrow) * RS) * 2u;
            } else {
                src = g.Bt + (size_t)(col0 + lrow) * ldb + (size_t)c * KS;
                dst = shb + (boff + (uint32_t)((bi * 64 + lrow) * RS)) * 2u;
            }
            bulk_cp(dst, src, (uint32_t)KS * 2u, mbar);
        }
    };

    float acc[2][2][4];
    #pragma unroll
    for (int i = 0; i < 2; ++i)
        #pragma unroll
        for (int j2 = 0; j2 < 2; ++j2)
            #pragma unroll
            for (int k2 = 0; k2 < 4; ++k2) acc[i][j2][k2] = 0.f;

    int ph0 = 0, ph1 = 0;
    issue(0);

    const int j   = lane & 7;
    const int sm8 = (lane >> 3) & 1;
    const int sk8 = (lane >> 4) & 1;

    for (int c = 0; c < ns; ++c) {
        if (c + 1 < ns) issue(c + 1);
        if ((c & 1) == 0) { MBAR_WAIT(mb,     ph0); ph0 ^= 1; }
        else              { MBAR_WAIT(mb + 8, ph1); ph1 ^= 1; }

        const int bi = c & (bufs - 1);
        const uint32_t Ab = shb + (uint32_t)(bi * 64 * RS) * 2u;
        const uint32_t Bb = shb + (boff + (uint32_t)(bi * 64 * RS)) * 2u;
        const int steps = KS >> 4;

        const uint32_t arow_off = (uint32_t)((wm * 32 + j + 8 * sm8) * RS + 8 * sk8) * 2u;
        const uint32_t brow_off = (uint32_t)((wn * 16 + j + 8 * sm8) * RS + 8 * sk8) * 2u;

        for (int s = 0; s < steps; ++s) {
            const uint32_t kb2 = (uint32_t)(s * 16) * 2u;
            uint32_t a0[4], a1[4], bb[4];
            ldsm_x4(a0, Ab + arow_off + kb2);
            ldsm_x4(a1, Ab + arow_off + kb2 + (uint32_t)(16 * RS) * 2u);
            ldsm_x4(bb, Bb + brow_off + kb2);
            mma16(acc[0][0], a0, bb[0], bb[2]);
            mma16(acc[0][1], a0, bb[1], bb[3]);
            mma16(acc[1][0], a1, bb[0], bb[2]);
            mma16(acc[1][1], a1, bb[1], bb[3]);
        }
        __syncthreads();
    }

    // ---- epilogue ----
    float bv[2][2];
    #pragma unroll
    for (int nt = 0; nt < 2; ++nt) {
        const int cc = col0 + wn * 16 + nt * 8 + r * 2;
        bv[nt][0] = g.bias ? __ldg(g.bias + cc)     : 0.f;
        bv[nt][1] = g.bias ? __ldg(g.bias + cc + 1) : 0.f;
    }
    #pragma unroll
    for (int mt = 0; mt < 2; ++mt) {
        #pragma unroll
        for (int rh = 0; rh < 2; ++rh) {
            const int rr = row0 + wm * 32 + mt * 16 + rh * 8 + q;
            if (rr >= M) continue;
            #pragma unroll
            for (int nt = 0; nt < 2; ++nt) {
                const int cc = col0 + wn * 16 + nt * 8 + r * 2;
                const float ox = acc[mt][nt][rh * 2 + 0] + bv[nt][0];
                const float oy = acc[mt][nt][rh * 2 + 1] + bv[nt][1];
                if (omode == 2) {
                    __half2* dp = (__half2*)(g.Ch + (size_t)rr * ldc + cc);
                    *dp = __floats2half2_rn(ox, oy);
                } else {
                    float* rowp;
                    if (omode == 0) rowp = g.C + (size_t)rr * ldc;
                    else {
                        const int t = rr % S_, bbn = rr / S_;
                        rowp = g.C + (size_t)t * (B_ * D_) + (size_t)bbn * D_;
                    }
                    *(float2*)(rowp + cc) = make_float2(ox, oy);
                }
            }
        }
    }
}

// ---------------------------------------------------------------------------
// Fused prep: blockIdx.z selects job.
//  z=0..4: transpose+convert (Wq, Wc, Wout, mem b0, mem b1)
//  z=5:    f32->f16 convert of input & memory
// grid (16, 32, 6), 256 threads.
// ---------------------------------------------------------------------------
__global__ void prep_kernel(
    const float* __restrict__ input, const float* __restrict__ memory,
    const float* __restrict__ Wq, const float* __restrict__ Wc,
    const float* __restrict__ Wout,
    __half* __restrict__ in_h, __half* __restrict__ mem_h,
    __half* __restrict__ WqT, __half* __restrict__ WcT,
    __half* __restrict__ WoutT, __half* __restrict__ memT)
{
    const int z = blockIdx.z;
    const int tid = threadIdx.x;

    if (z == 5) {   // conv job
        const int i = (blockIdx.y * 16 + blockIdx.x) * 256 + tid;
        const int n4 = ROWS * D_ / 4;
        if (i < n4) {
            float4 v = ((const float4*)input)[i];
            ((__half2*)in_h)[2 * i]     = __floats2half2_rn(v.x, v.y);
            ((__half2*)in_h)[2 * i + 1] = __floats2half2_rn(v.z, v.w);
            v = ((const float4*)memory)[i];
            ((__half2*)mem_h)[2 * i]     = __floats2half2_rn(v.x, v.y);
            ((__half2*)mem_h)[2 * i + 1] = __floats2half2_rn(v.z, v.w);
        }
        return;
    }

    const float* I; __half* O; int R; int ylim;
    switch (z) {
        case 0: I = Wq;   O = WqT;   R = 512;  ylim = 16; break;
        case 1: I = Wc;   O = WcT;   R = 512;  ylim = 16; break;
        case 2: I = Wout; O = WoutT; R = 1024; ylim = 32; break;
        case 3: I = memory;            O = memT;            R = 400; ylim = 13; break;
        default:I = memory + 400 * 512; O = memT + 512 * 400; R = 400; ylim = 13; break;
    }
    if ((int)blockIdx.y >= ylim) return;
    const int C = 512;

    __shared__ float t[32][33];
    const int c0 = blockIdx.x * 32, r0 = blockIdx.y * 32;
    const int x = tid & 31, y = tid >> 5;    // 32 x 8
    #pragma unroll
    for (int d = 0; d < 32; d += 8) {
        const int rr = r0 + y + d, cc = c0 + x;
        t[y + d][x] = (rr < R && cc < C) ? I[(size_t)rr * C + cc] : 0.f;
    }
    __syncthreads();
    #pragma unroll
    for (int d = 0; d < 32; d += 8) {
        const int orow = c0 + y + d;   // original col
        const int ocol = r0 + x;       // original row
        if (orow < C && ocol < R)
            O[(size_t)orow * R + ocol] = __float2half(t[x][y + d]);
    }
}

// ---------------------------------------------------------------------------
// FUSED scores + masked softmax.
// CTA = 2 t-rows x full s-range. grid (200, 2), 256 threads (8 warps).
// Phase 1: scores into smem (HADD2 + tanh.f16x2 + HFMA2, f32 flush).
// Phase 2: per-row masked softmax from smem; writes align f32 (d_out) + f16.
// ---------------------------------------------------------------------------
__global__ void __launch_bounds__(256) scores_softmax_kernel(
    const __half2* __restrict__ wq, const __half2* __restrict__ uh,
    const float* __restrict__ v, const int* __restrict__ lens,
    float* __restrict__ align_out, __half* __restrict__ align_h)
{
    const int b = blockIdx.y;
    const int t0 = blockIdx.x * 2;
    const int len = lens[b];

    __shared__ __half2 qsm[2][D_ / 2];
    __shared__ __half2 vsm[D_ / 2];
    __shared__ float   ssm[2][S_];
    __shared__ float   red[2][8];

    const int tid = threadIdx.x;
    for (int i = tid; i < 2 * (D_ / 2); i += 256)
        qsm[i >> 8][i & 255] = wq[((size_t)(b * S_ + t0 + (i >> 8))) * (D_ / 2) + (i & 255)];
    for (int i = tid; i < D_ / 2; i += 256)
        vsm[i] = __floats2half2_rn(v[2 * i], v[2 * i + 1]);
    __syncthreads();

    const int warp = tid >> 5, lane = tid & 31;

    // ---- Phase 1: scores for s in [0, len), 32 s per pass (4 per warp) ----
    for (int pass = 0; ; ++pass) {
        const int s0 = pass * 32 + warp * 4;
        if (pass * 32 >= len) break;            // uniform across warps
        if (s0 < len) {
            const __half2* up[4];
            #pragma unroll
            for (int j = 0; j < 4; ++j) {
                int sj = s0 + j; if (sj > S_ - 1) sj = S_ - 1;
                up[j] = uh + ((size_t)b * S_ + sj) * (D_ / 2);
            }
            float acc[2][4];
            __half2 acc2[2][4];
            const __half2 h2z = __floats2half2_rn(0.f, 0.f);
            #pragma unroll
            for (int t = 0; t < 2; ++t)
                #pragma unroll
                for (int j = 0; j < 4; ++j) { acc[t][j] = 0.f; acc2[t][j] = h2z; }

            #pragma unroll
            for (int i = 0; i < 8; ++i) {
                const int e2 = i * 32 + lane;
                const __half2 v2 = vsm[e2];
                __half2 q2[2];
                q2[0] = qsm[0][e2];
                q2[1] = qsm[1][e2];
                #pragma unroll
                for (int j = 0; j < 4; ++j) {
                    const __half2 u2 = __ldg(up[j] + e2);
                    acc2[0][j] = __hfma2(v2, tanh2_fast(__hadd2(q2[0], u2)), acc2[0][j]);
                    acc2[1][j] = __hfma2(v2, tanh2_fast(__hadd2(q2[1], u2)), acc2[1][j]);
                }
                if ((i & 3) == 3) {
                    #pragma unroll
                    for (int t = 0; t < 2; ++t)
                        #pragma unroll
                        for (int j = 0; j < 4; ++j) {
                            const float2 f = __half22float2(acc2[t][j]);
                            acc[t][j] += f.x + f.y;
                            acc2[t][j] = h2z;
                        }
                }
            }
            #pragma unroll
            for (int t = 0; t < 2; ++t)
                #pragma unroll
                for (int j = 0; j < 4; ++j) {
                    float a = acc[t][j];
                    a += __shfl_xor_sync(0xffffffffu, a, 16);
                    a += __shfl_xor_sync(0xffffffffu, a, 8);
                    a += __shfl_xor_sync(0xffffffffu, a, 4);
                    a += __shfl_xor_sync(0xffffffffu, a, 2);
                    a += __shfl_xor_sync(0xffffffffu, a, 1);
                    if (lane == t * 4 + j && s0 + j < len)
                        ssm[t][s0 + j] = a;
                }
        }
    }
    __syncthreads();

    // ---- Phase 2: masked softmax, 4 warps per row ----
    const int ti = warp >> 2;            // 0..1
    const int wr = warp & 3;             // warp within row
    const int tg = t0 + ti;              // global t
    float vals[4];
    float mx = -1e30f;
    #pragma unroll
    for (int k = 0; k < 4; ++k) {
        const int s = k * 128 + wr * 32 + lane;   // covers 0..511
        const bool ok = (s < len) && (s != tg);
        const float val = ok ? ssm[ti][s] : -1e30f;
        vals[k] = val;
        mx = fmaxf(mx, val);
    }
    #pragma unroll
    for (int o = 16; o; o >>= 1) mx = fmaxf(mx, __shfl_xor_sync(0xffffffffu, mx, o));
    if (lane == 0) red[ti][wr] = mx;
    __syncthreads();
    mx = fmaxf(fmaxf(red[ti][0], red[ti][1]), fmaxf(red[ti][2], red[ti][3]));

    float sum = 0.f;
    #pragma unroll
    for (int k = 0; k < 4; ++k) {
        const float e = (vals[k] > -1e29f) ? __expf(vals[k] - mx) : 0.f;
        vals[k] = e;
        sum += e;
    }
    #pragma unroll
    for (int o = 16; o; o >>= 1) sum += __shfl_xor_sync(0xffffffffu, sum, o);
    if (lane == 0) red[ti][4 + wr] = sum;
    __syncthreads();
    const float inv = 1.0f / (red[ti][4] + red[ti][5] + red[ti][6] + red[ti][7]);

    const size_t obase = (size_t)tg * (B_ * S_) + (size_t)b * S_;
    #pragma unroll
    for (int k = 0; k < 4; ++k) {
        const int s = k * 128 + wr * 32 + lane;
        if (s < S_) {
            const float a = vals[k] * inv;
            align_out[obase + s] = a;
            align_h[obase + s]   = __float2half(a);
        }
    }
}

// ---------------------------------------------------------------------------
extern "C" void kernel_launch(void* const* d_in, const int* in_sizes, int n_in,
                              void* d_out, int out_size)
{
    const float* input  = (const float*)d_in[0];
    const float* memory = (const float*)d_in[1];
    const int*   lens   = (const int*)d_in[2];
    const float* Wq     = (const float*)d_in[3];
    const float* bq     = (const float*)d_in[4];
    const float* Wc     = (const float*)d_in[5];
    const float* v      = (const float*)d_in[6];
    const float* Wout   = (const float*)d_in[7];
    const float* bout   = (const float*)d_in[8];
    float* out = (float*)d_out;

    __half *wq_h, *uh_h, *in_h, *mem_h, *memT_h, *WqT, *WcT, *WoutT, *ctx_h, *align_h;
    cudaGetSymbolAddress((void**)&wq_h,    g_wq_h);
    cudaGetSymbolAddress((void**)&uh_h,    g_uh_h);
    cudaGetSymbolAddress((void**)&in_h,    g_in_h);
    cudaGetSymbolAddress((void**)&mem_h,   g_mem_h);
    cudaGetSymbolAddress((void**)&memT_h,  g_memT_h);
    cudaGetSymbolAddress((void**)&WqT,     g_WqT);
    cudaGetSymbolAddress((void**)&WcT,     g_WcT);
    cudaGetSymbolAddress((void**)&WoutT,   g_WoutT);
    cudaGetSymbolAddress((void**)&ctx_h,   g_ctx_h);
    cudaGetSymbolAddress((void**)&align_h, g_align_h);

    static bool attr_set = false;
    if (!attr_set) {
        cudaFuncSetAttribute(gemm_f16, cudaFuncAttributeMaxDynamicSharedMemorySize,
                             2 * 2 * 64 * (256 + 8) * 2);   // 135168
        attr_set = true;
    }

    // ---- prep (fused: 4 transposes + f32->f16 conversions) ----
    prep_kernel<<<dim3(16, 32, 6), 256>>>(
        input, memory, Wq, Wc, Wout, in_h, mem_h, WqT, WcT, WoutT, memT_h);

    // ---- 1) fused: z=0 -> wq_h = input@Wq + bq; z=1 -> uh_h = memory@Wc (f16 out)
    {
        GemmArgs gq{in_h,  in_h,  WqT, bq,      nullptr, wq_h};
        GemmArgs gu{mem_h, mem_h, WcT, nullptr, nullptr, uh_h};
        gemm_f16<<<dim3(8, 13, 2), 256, 2 * 2 * 64 * 264 * 2>>>(
            gq, gu, 512, 512, 512, 512, 2, 800, 512, 256, 2);
    }
    // ---- 2) fused scores + softmax -> align (f32 in d_out, f16 copy) ----
    scores_softmax_kernel<<<dim3(200, 2), 256>>>(
        (const __half2*)wq_h, (const __half2*)uh_h, v, lens,
        out + ALIGN_OFF, align_h);
    // ---- 3) context: c[b] = align[b] @ memory[b] -> ctx_h (f16) ----
    {
        GemmArgs c0{align_h,       align_h,       memT_h,             nullptr, nullptr, ctx_h};
        GemmArgs c1{align_h + S_,  align_h + S_,  memT_h + D_ * S_,   nullptr, nullptr, ctx_h + S_ * D_};
        gemm_f16<<<dim3(8, 7, 2), 256, 1 * 2 * 64 * 408 * 2>>>(
            c0, c1, 800, 400, 400, 512, 2, 400, 400, 400, 1);
    }
    // ---- 4) attn_h = [ctx | input] @ Wout + bout -> [T,B,D] in d_out ----
    {
        GemmArgs go{ctx_h, in_h, WoutT, bout, out, nullptr};
        gemm_f16<<<dim3(8, 13, 1), 256, 2 * 2 * 64 * 264 * 2>>>(
            go, go, 512, 512, 1024, 512, 1, 800, 1024, 256, 2);
    }
}